// round 2
// baseline (speedup 1.0000x reference)
#include <cuda_runtime.h>

#define B_ 4
#define T_ 2048
#define C_ 768
#define H_ 12
#define D_ 64

// Scratch (allocation-guard-safe device globals)
__device__ float g_q[B_ * T_ * C_];
__device__ float g_k[B_ * T_ * C_];
__device__ float g_v[B_ * T_ * C_];
__device__ float g_att[B_ * T_ * C_];

// ---------------------------------------------------------------------------
// Tiled SGEMM: out[m,n] = sum_k A[m,k] * W[n,k] (+ bias[n])
// 64x64 block tile, K-panel 16, 256 threads, 4x4 per-thread micro-tile.
// ---------------------------------------------------------------------------
__global__ __launch_bounds__(256) void gemm_bias_kernel(
    const float* __restrict__ A, const float* __restrict__ W,
    const float* __restrict__ bias, float* __restrict__ out,
    int M, int N, int K)
{
    __shared__ float As[16][68];  // [k][m]
    __shared__ float Bs[16][68];  // [k][n]

    const int tid = threadIdx.x;
    const int tx = tid & 15;       // n group
    const int ty = tid >> 4;       // m group
    const int m0 = blockIdx.y * 64;
    const int n0 = blockIdx.x * 64;

    const int lr = tid >> 2;        // 0..63 (tile row)
    const int lk = (tid & 3) * 4;   // 0,4,8,12 (k offset)

    const float* Ap = A + (size_t)(m0 + lr) * K + lk;
    const float* Wr = W + (size_t)(n0 + lr) * K + lk;

    float acc[4][4] = {};

    for (int k0 = 0; k0 < K; k0 += 16) {
        float4 av = *(const float4*)(Ap + k0);
        float4 wv = *(const float4*)(Wr + k0);
        __syncthreads();
        As[lk + 0][lr] = av.x; As[lk + 1][lr] = av.y;
        As[lk + 2][lr] = av.z; As[lk + 3][lr] = av.w;
        Bs[lk + 0][lr] = wv.x; Bs[lk + 1][lr] = wv.y;
        Bs[lk + 2][lr] = wv.z; Bs[lk + 3][lr] = wv.w;
        __syncthreads();

        #pragma unroll
        for (int kk = 0; kk < 16; kk++) {
            float4 a = *(const float4*)(&As[kk][ty * 4]);
            float4 b = *(const float4*)(&Bs[kk][tx * 4]);
            float ar[4] = {a.x, a.y, a.z, a.w};
            float br[4] = {b.x, b.y, b.z, b.w};
            #pragma unroll
            for (int i = 0; i < 4; i++)
                #pragma unroll
                for (int j = 0; j < 4; j++)
                    acc[i][j] += ar[i] * br[j];
        }
    }

    float bj[4] = {0.f, 0.f, 0.f, 0.f};
    if (bias) {
        #pragma unroll
        for (int j = 0; j < 4; j++) bj[j] = bias[n0 + tx * 4 + j];
    }
    #pragma unroll
    for (int i = 0; i < 4; i++)
        #pragma unroll
        for (int j = 0; j < 4; j++)
            out[(size_t)(m0 + ty * 4 + i) * N + n0 + tx * 4 + j] = acc[i][j] + bj[j];
}

// ---------------------------------------------------------------------------
// Flash attention: one CTA per (q-tile of 64 rows, head, batch).
// q/k/v are [B,T,C] with head slice at column h*D. D = 64.
// ---------------------------------------------------------------------------
__global__ __launch_bounds__(256) void attn_kernel(
    const float* __restrict__ Qg, const float* __restrict__ Kg,
    const float* __restrict__ Vg, float* __restrict__ Og)
{
    extern __shared__ float sm[];
    const int S = 68;
    float* Qs  = sm;             // [d][r], pre-scaled
    float* KVs = sm + 64 * S;    // K: [d][c]; then V: [k][d]
    float* Ps  = sm + 128 * S;   // [k][r]

    const int tid = threadIdx.x;
    const int tx = tid & 15;   // column group of S / d group of O
    const int ty = tid >> 4;   // row group
    const int qt = blockIdx.x * 64;
    const int h = blockIdx.y;
    const int b = blockIdx.z;
    const size_t base = ((size_t)b * T_) * C_ + (size_t)h * D_;
    const float scale = 0.125f;  // 1/sqrt(64)

    const int lr = tid >> 4;         // 0..15
    const int ld = (tid & 15) * 4;   // 0..60

    // Load Q tile transposed into [d][r], pre-scaled.
    #pragma unroll
    for (int rr = 0; rr < 4; rr++) {
        int r = lr + rr * 16;
        float4 qv = *(const float4*)(Qg + base + (size_t)(qt + r) * C_ + ld);
        Qs[(ld + 0) * S + r] = qv.x * scale;
        Qs[(ld + 1) * S + r] = qv.y * scale;
        Qs[(ld + 2) * S + r] = qv.z * scale;
        Qs[(ld + 3) * S + r] = qv.w * scale;
    }

    float mrow[4], lrow[4] = {0.f, 0.f, 0.f, 0.f};
    float o[4][4] = {};
    #pragma unroll
    for (int i = 0; i < 4; i++) mrow[i] = -1e30f;

    for (int kt = 0; kt < T_; kt += 64) {
        __syncthreads();  // previous iteration's KVs/Ps readers done

        // Load K tile transposed into [d][c]
        #pragma unroll
        for (int rr = 0; rr < 4; rr++) {
            int r = lr + rr * 16;
            float4 kv = *(const float4*)(Kg + base + (size_t)(kt + r) * C_ + ld);
            KVs[(ld + 0) * S + r] = kv.x;
            KVs[(ld + 1) * S + r] = kv.y;
            KVs[(ld + 2) * S + r] = kv.z;
            KVs[(ld + 3) * S + r] = kv.w;
        }
        __syncthreads();

        // S = (Q*scale) @ K^T : outer product over d
        float s[4][4] = {};
        #pragma unroll 8
        for (int d = 0; d < 64; d++) {
            float4 a = *(const float4*)(Qs + d * S + ty * 4);
            float4 bb = *(const float4*)(KVs + d * S + tx * 4);
            float ar[4] = {a.x, a.y, a.z, a.w};
            float br[4] = {bb.x, bb.y, bb.z, bb.w};
            #pragma unroll
            for (int i = 0; i < 4; i++)
                #pragma unroll
                for (int j = 0; j < 4; j++)
                    s[i][j] += ar[i] * br[j];
        }

        // Online softmax (row stats across the 16 tx lanes)
        #pragma unroll
        for (int i = 0; i < 4; i++) {
            float tm = fmaxf(fmaxf(s[i][0], s[i][1]), fmaxf(s[i][2], s[i][3]));
            #pragma unroll
            for (int off = 8; off > 0; off >>= 1)
                tm = fmaxf(tm, __shfl_xor_sync(0xffffffffu, tm, off));
            float mn = fmaxf(mrow[i], tm);
            float al = __expf(mrow[i] - mn);
            float sum = 0.f;
            #pragma unroll
            for (int j = 0; j < 4; j++) {
                s[i][j] = __expf(s[i][j] - mn);
                sum += s[i][j];
            }
            #pragma unroll
            for (int off = 8; off > 0; off >>= 1)
                sum += __shfl_xor_sync(0xffffffffu, sum, off);
            lrow[i] = lrow[i] * al + sum;
            mrow[i] = mn;
            #pragma unroll
            for (int j = 0; j < 4; j++) o[i][j] *= al;
        }

        // Stage P as [k][r]
        #pragma unroll
        for (int i = 0; i < 4; i++)
            #pragma unroll
            for (int j = 0; j < 4; j++)
                Ps[(tx * 4 + j) * S + ty * 4 + i] = s[i][j];
        __syncthreads();  // S-phase reads of KVs done; P visible

        // Load V tile natural [k][d] into KVs
        #pragma unroll
        for (int rr = 0; rr < 4; rr++) {
            int r = lr + rr * 16;
            float4 vv = *(const float4*)(Vg + base + (size_t)(kt + r) * C_ + ld);
            *(float4*)(KVs + r * S + ld) = vv;
        }
        __syncthreads();

        // O += P @ V : outer product over k
        #pragma unroll 8
        for (int k = 0; k < 64; k++) {
            float4 a = *(const float4*)(Ps + k * S + ty * 4);
            float4 bb = *(const float4*)(KVs + k * S + tx * 4);
            float ar[4] = {a.x, a.y, a.z, a.w};
            float br[4] = {bb.x, bb.y, bb.z, bb.w};
            #pragma unroll
            for (int i = 0; i < 4; i++)
                #pragma unroll
                for (int j = 0; j < 4; j++)
                    o[i][j] += ar[i] * br[j];
        }
    }

    // Normalize and write to [B,T,C] layout
    #pragma unroll
    for (int i = 0; i < 4; i++) {
        float inv = 1.0f / lrow[i];
        #pragma unroll
        for (int j = 0; j < 4; j++)
            Og[base + (size_t)(qt + ty * 4 + i) * C_ + tx * 4 + j] = o[i][j] * inv;
    }
}

// ---------------------------------------------------------------------------
extern "C" void kernel_launch(void* const* d_in, const int* in_sizes, int n_in,
                              void* d_out, int out_size)
{
    const float* x  = (const float*)d_in[0];
    const float* Wq = (const float*)d_in[1];
    const float* bq = (const float*)d_in[2];
    const float* Wk = (const float*)d_in[3];
    const float* bk = (const float*)d_in[4];
    const float* Wv = (const float*)d_in[5];
    const float* bv = (const float*)d_in[6];
    const float* Wp = (const float*)d_in[7];
    float* out = (float*)d_out;

    float *q, *k, *v, *att;
    cudaGetSymbolAddress((void**)&q,   g_q);
    cudaGetSymbolAddress((void**)&k,   g_k);
    cudaGetSymbolAddress((void**)&v,   g_v);
    cudaGetSymbolAddress((void**)&att, g_att);

    const int M = B_ * T_;
    dim3 ggrid(C_ / 64, M / 64);

    gemm_bias_kernel<<<ggrid, 256>>>(x, Wq, bq, q, M, C_, C_);
    gemm_bias_kernel<<<ggrid, 256>>>(x, Wk, bk, k, M, C_, C_);
    gemm_bias_kernel<<<ggrid, 256>>>(x, Wv, bv, v, M, C_, C_);

    const int attn_smem = 3 * 64 * 68 * (int)sizeof(float);  // 52224 B
    cudaFuncSetAttribute(attn_kernel,
                         cudaFuncAttributeMaxDynamicSharedMemorySize, attn_smem);
    attn_kernel<<<dim3(T_ / 64, H_, B_), 256, attn_smem>>>(q, k, v, att);

    gemm_bias_kernel<<<ggrid, 256>>>(att, Wp, nullptr, out, M, C_, C_);
}

// round 3
// speedup vs baseline: 2.1261x; 2.1261x over previous
#include <cuda_runtime.h>

#define B_ 4
#define T_ 2048
#define C_ 768
#define H_ 12
#define D_ 64

// Scratch (allocation-guard-safe device globals)
__device__ float g_q[B_ * T_ * C_];
__device__ float g_k[B_ * T_ * C_];
__device__ float g_v[B_ * T_ * C_];
__device__ float g_att[B_ * T_ * C_];

__device__ __forceinline__ unsigned f2tf32(float x) {
    unsigned r;
    asm("cvt.rna.tf32.f32 %0, %1;" : "=r"(r) : "f"(x));
    return r;
}

__device__ __forceinline__ void mma8(float* d, const unsigned* a,
                                     const unsigned* b, const float* c) {
    asm volatile(
        "mma.sync.aligned.m16n8k8.row.col.f32.tf32.tf32.f32 "
        "{%0,%1,%2,%3},{%4,%5,%6,%7},{%8,%9},{%10,%11,%12,%13};\n"
        : "=f"(d[0]), "=f"(d[1]), "=f"(d[2]), "=f"(d[3])
        : "r"(a[0]), "r"(a[1]), "r"(a[2]), "r"(a[3]),
          "r"(b[0]), "r"(b[1]),
          "f"(c[0]), "f"(c[1]), "f"(c[2]), "f"(c[3]));
}

// ---------------------------------------------------------------------------
// TF32 GEMM: out[m,n] = sum_k A[m,k]*W[n,k] (+bias[n]); N=K=768 fixed.
// CTA tile 128x64, K-chunk 32, 256 threads (8 warps, 4x2 warp grid, 32x32/warp)
// ---------------------------------------------------------------------------
#define GP 36
__global__ __launch_bounds__(256) void gemm_tf32(
    const float* __restrict__ A, const float* __restrict__ W,
    const float* __restrict__ bias, float* __restrict__ out, int M)
{
    __shared__ unsigned As[128 * GP];
    __shared__ unsigned Bs[64 * GP];

    const int tid = threadIdx.x;
    const int m0 = blockIdx.y * 128, n0 = blockIdx.x * 64;
    const int warp = tid >> 5, lane = tid & 31;
    const int g = lane >> 2, q = lane & 3;
    const int wm = (warp & 3) * 32, wn = (warp >> 2) * 32;

    float acc[2][4][4] = {};

    const int ar = tid >> 3;          // 0..31
    const int ac = (tid & 7) * 4;     // 0..28

    for (int k0 = 0; k0 < 768; k0 += 32) {
        __syncthreads();
        #pragma unroll
        for (int p = 0; p < 4; p++) {
            float4 v = *(const float4*)(A + (size_t)(m0 + ar + p * 32) * 768 + k0 + ac);
            uint4 t = {f2tf32(v.x), f2tf32(v.y), f2tf32(v.z), f2tf32(v.w)};
            *(uint4*)(&As[(ar + p * 32) * GP + ac]) = t;
        }
        #pragma unroll
        for (int p = 0; p < 2; p++) {
            float4 v = *(const float4*)(W + (size_t)(n0 + ar + p * 32) * 768 + k0 + ac);
            uint4 t = {f2tf32(v.x), f2tf32(v.y), f2tf32(v.z), f2tf32(v.w)};
            *(uint4*)(&Bs[(ar + p * 32) * GP + ac]) = t;
        }
        __syncthreads();

        #pragma unroll
        for (int kk = 0; kk < 4; kk++) {
            unsigned a[2][4], b[4][2];
            #pragma unroll
            for (int mi = 0; mi < 2; mi++) {
                const unsigned* p = &As[(wm + mi * 16) * GP + kk * 8];
                a[mi][0] = p[g * GP + q];
                a[mi][1] = p[(g + 8) * GP + q];
                a[mi][2] = p[g * GP + q + 4];
                a[mi][3] = p[(g + 8) * GP + q + 4];
            }
            #pragma unroll
            for (int ni = 0; ni < 4; ni++) {
                const unsigned* p = &Bs[(wn + ni * 8 + g) * GP + kk * 8];
                b[ni][0] = p[q];
                b[ni][1] = p[q + 4];
            }
            #pragma unroll
            for (int mi = 0; mi < 2; mi++)
                #pragma unroll
                for (int ni = 0; ni < 4; ni++)
                    mma8(acc[mi][ni], a[mi], b[ni], acc[mi][ni]);
        }
    }

    #pragma unroll
    for (int ni = 0; ni < 4; ni++) {
        int col = n0 + wn + ni * 8 + 2 * q;
        float b0 = bias ? bias[col] : 0.f;
        float b1 = bias ? bias[col + 1] : 0.f;
        #pragma unroll
        for (int mi = 0; mi < 2; mi++) {
            int row = m0 + wm + mi * 16 + g;
            float2 v0 = {acc[mi][ni][0] + b0, acc[mi][ni][1] + b1};
            float2 v1 = {acc[mi][ni][2] + b0, acc[mi][ni][3] + b1};
            *(float2*)(out + (size_t)row * 768 + col) = v0;
            *(float2*)(out + (size_t)(row + 8) * 768 + col) = v1;
        }
    }
}

// ---------------------------------------------------------------------------
// TF32 flash attention. CTA = 64 q-rows x (head, batch). 128 threads, 4 warps,
// each warp owns 16 q-rows. K tile 64. D = 64. smem: Q | K(/P) | V^T, tf32.
// ---------------------------------------------------------------------------
#define SP 68
__global__ __launch_bounds__(128) void attn_tf32(
    const float* __restrict__ Qg, const float* __restrict__ Kg,
    const float* __restrict__ Vg, float* __restrict__ Og)
{
    extern __shared__ unsigned sm[];
    unsigned* Qs = sm;                 // [m][k] 64x64, pre-scaled
    unsigned* Ks = sm + 64 * SP;       // [n][k] 64x64; reused as P [m][k]
    unsigned* Vs = sm + 2 * 64 * SP;   // [d][k] 64x64 (V transposed)

    const int tid = threadIdx.x;
    const int warp = tid >> 5, lane = tid & 31;
    const int g = lane >> 2, q = lane & 3;
    const int wm = warp * 16;
    const int qt = blockIdx.x * 64;
    const int h = blockIdx.y, b = blockIdx.z;
    const size_t base = ((size_t)b * T_) * C_ + (size_t)h * D_;

    const int lr = tid >> 1;           // 0..63 (tile row)
    const int dc = (tid & 1) * 32;     // 0 or 32

    // Q tile, pre-scaled by 1/sqrt(D), tf32
    #pragma unroll
    for (int j = 0; j < 8; j++) {
        float4 v = *(const float4*)(Qg + base + (size_t)(qt + lr) * C_ + dc + j * 4);
        uint4 t = {f2tf32(v.x * 0.125f), f2tf32(v.y * 0.125f),
                   f2tf32(v.z * 0.125f), f2tf32(v.w * 0.125f)};
        *(uint4*)(&Qs[lr * SP + dc + j * 4]) = t;
    }

    float m0r = -1e30f, m1r = -1e30f, l0 = 0.f, l1 = 0.f;
    float ofr[8][4] = {};

    for (int kt = 0; kt < T_; kt += 64) {
        __syncthreads();
        // K natural [t][d] -> Ks[n][k]
        #pragma unroll
        for (int j = 0; j < 8; j++) {
            float4 v = *(const float4*)(Kg + base + (size_t)(kt + lr) * C_ + dc + j * 4);
            uint4 t = {f2tf32(v.x), f2tf32(v.y), f2tf32(v.z), f2tf32(v.w)};
            *(uint4*)(&Ks[lr * SP + dc + j * 4]) = t;
        }
        // V transposed -> Vs[d][t]
        #pragma unroll
        for (int j = 0; j < 8; j++) {
            float4 v = *(const float4*)(Vg + base + (size_t)(kt + lr) * C_ + dc + j * 4);
            Vs[(dc + j * 4 + 0) * SP + lr] = f2tf32(v.x);
            Vs[(dc + j * 4 + 1) * SP + lr] = f2tf32(v.y);
            Vs[(dc + j * 4 + 2) * SP + lr] = f2tf32(v.z);
            Vs[(dc + j * 4 + 3) * SP + lr] = f2tf32(v.w);
        }
        __syncthreads();

        // S = Q @ K^T  (warp: rows [wm, wm+16), all 64 cols)
        float sfr[8][4] = {};
        #pragma unroll
        for (int kk = 0; kk < 8; kk++) {
            unsigned a[4];
            const unsigned* qp = &Qs[wm * SP + kk * 8];
            a[0] = qp[g * SP + q];
            a[1] = qp[(g + 8) * SP + q];
            a[2] = qp[g * SP + q + 4];
            a[3] = qp[(g + 8) * SP + q + 4];
            #pragma unroll
            for (int ni = 0; ni < 8; ni++) {
                unsigned bb[2];
                const unsigned* kp = &Ks[(ni * 8 + g) * SP + kk * 8];
                bb[0] = kp[q];
                bb[1] = kp[q + 4];
                mma8(sfr[ni], a, bb, sfr[ni]);
            }
        }

        // Online softmax. Thread holds rows (wm+g, wm+g+8), cols ni*8+2q(+1).
        float mx0 = -1e30f, mx1 = -1e30f;
        #pragma unroll
        for (int ni = 0; ni < 8; ni++) {
            mx0 = fmaxf(mx0, fmaxf(sfr[ni][0], sfr[ni][1]));
            mx1 = fmaxf(mx1, fmaxf(sfr[ni][2], sfr[ni][3]));
        }
        #pragma unroll
        for (int off = 1; off <= 2; off <<= 1) {
            mx0 = fmaxf(mx0, __shfl_xor_sync(0xffffffffu, mx0, off));
            mx1 = fmaxf(mx1, __shfl_xor_sync(0xffffffffu, mx1, off));
        }
        float mn0 = fmaxf(m0r, mx0), mn1 = fmaxf(m1r, mx1);
        float al0 = __expf(m0r - mn0), al1 = __expf(m1r - mn1);
        m0r = mn0; m1r = mn1;
        float s0 = 0.f, s1 = 0.f;
        #pragma unroll
        for (int ni = 0; ni < 8; ni++) {
            sfr[ni][0] = __expf(sfr[ni][0] - mn0);
            sfr[ni][1] = __expf(sfr[ni][1] - mn0);
            sfr[ni][2] = __expf(sfr[ni][2] - mn1);
            sfr[ni][3] = __expf(sfr[ni][3] - mn1);
            s0 += sfr[ni][0] + sfr[ni][1];
            s1 += sfr[ni][2] + sfr[ni][3];
        }
        #pragma unroll
        for (int off = 1; off <= 2; off <<= 1) {
            s0 += __shfl_xor_sync(0xffffffffu, s0, off);
            s1 += __shfl_xor_sync(0xffffffffu, s1, off);
        }
        l0 = l0 * al0 + s0;
        l1 = l1 * al1 + s1;
        #pragma unroll
        for (int ni = 0; ni < 8; ni++) {
            ofr[ni][0] *= al0; ofr[ni][1] *= al0;
            ofr[ni][2] *= al1; ofr[ni][3] *= al1;
        }

        __syncthreads();  // all warps done reading Ks
        // Stage P (tf32) into Ks region as [m][k]
        #pragma unroll
        for (int ni = 0; ni < 8; ni++) {
            uint2 p0 = {f2tf32(sfr[ni][0]), f2tf32(sfr[ni][1])};
            uint2 p1 = {f2tf32(sfr[ni][2]), f2tf32(sfr[ni][3])};
            *(uint2*)(&Ks[(wm + g) * SP + ni * 8 + 2 * q]) = p0;
            *(uint2*)(&Ks[(wm + g + 8) * SP + ni * 8 + 2 * q]) = p1;
        }
        __syncthreads();

        // O += P @ V  (A = P [m][k], B = Vs [n=d][k])
        #pragma unroll
        for (int kk = 0; kk < 8; kk++) {
            unsigned a[4];
            const unsigned* pp = &Ks[wm * SP + kk * 8];
            a[0] = pp[g * SP + q];
            a[1] = pp[(g + 8) * SP + q];
            a[2] = pp[g * SP + q + 4];
            a[3] = pp[(g + 8) * SP + q + 4];
            #pragma unroll
            for (int ni = 0; ni < 8; ni++) {
                unsigned bb[2];
                const unsigned* vp = &Vs[(ni * 8 + g) * SP + kk * 8];
                bb[0] = vp[q];
                bb[1] = vp[q + 4];
                mma8(ofr[ni], a, bb, ofr[ni]);
            }
        }
    }

    // Normalize + write [B,T,C]
    float inv0 = 1.0f / l0, inv1 = 1.0f / l1;
    #pragma unroll
    for (int ni = 0; ni < 8; ni++) {
        int col = ni * 8 + 2 * q;
        float2 v0 = {ofr[ni][0] * inv0, ofr[ni][1] * inv0};
        float2 v1 = {ofr[ni][2] * inv1, ofr[ni][3] * inv1};
        *(float2*)(Og + base + (size_t)(qt + wm + g) * C_ + col) = v0;
        *(float2*)(Og + base + (size_t)(qt + wm + g + 8) * C_ + col) = v1;
    }
}

// ---------------------------------------------------------------------------
extern "C" void kernel_launch(void* const* d_in, const int* in_sizes, int n_in,
                              void* d_out, int out_size)
{
    const float* x  = (const float*)d_in[0];
    const float* Wq = (const float*)d_in[1];
    const float* bq = (const float*)d_in[2];
    const float* Wk = (const float*)d_in[3];
    const float* bk = (const float*)d_in[4];
    const float* Wv = (const float*)d_in[5];
    const float* bv = (const float*)d_in[6];
    const float* Wp = (const float*)d_in[7];
    float* out = (float*)d_out;

    float *q, *k, *v, *att;
    cudaGetSymbolAddress((void**)&q,   g_q);
    cudaGetSymbolAddress((void**)&k,   g_k);
    cudaGetSymbolAddress((void**)&v,   g_v);
    cudaGetSymbolAddress((void**)&att, g_att);

    const int M = B_ * T_;
    dim3 ggrid(C_ / 64, M / 128);

    gemm_tf32<<<ggrid, 256>>>(x, Wq, bq, q, M);
    gemm_tf32<<<ggrid, 256>>>(x, Wk, bk, k, M);
    gemm_tf32<<<ggrid, 256>>>(x, Wv, bv, v, M);

    const int attn_smem = 3 * 64 * SP * (int)sizeof(unsigned);  // 52224 B
    cudaFuncSetAttribute(attn_tf32,
                         cudaFuncAttributeMaxDynamicSharedMemorySize, attn_smem);
    attn_tf32<<<dim3(T_ / 64, H_, B_), 128, attn_smem>>>(q, k, v, att);

    gemm_tf32<<<ggrid, 256>>>(att, Wp, nullptr, out, M);
}

// round 4
// speedup vs baseline: 6.5255x; 3.0692x over previous
#include <cuda_runtime.h>
#include <cuda_fp16.h>

#define B_ 4
#define T_ 2048
#define C_ 768
#define H_ 12
#define D_ 64
#define M_TOT (B_ * T_)

// fp16 scratch (allocation-guard-safe device globals)
__device__ __half g_xh[M_TOT * C_];
__device__ __half g_wq[C_ * C_], g_wk[C_ * C_], g_wv[C_ * C_], g_wp[C_ * C_];
__device__ __half g_qh[M_TOT * C_], g_kh[M_TOT * C_], g_vh[M_TOT * C_], g_ah[M_TOT * C_];

// ---------------------------------------------------------------------------
__global__ void f2h_kernel(const float* __restrict__ in, __half* __restrict__ out, int n4)
{
    int i = blockIdx.x * blockDim.x + threadIdx.x;
    if (i < n4) {
        float4 v = ((const float4*)in)[i];
        __half2 h0 = __floats2half2_rn(v.x, v.y);
        __half2 h1 = __floats2half2_rn(v.z, v.w);
        ((__half2*)out)[2 * i]     = h0;
        ((__half2*)out)[2 * i + 1] = h1;
    }
}

// ---------------------------------------------------------------------------
__device__ __forceinline__ unsigned sa(const void* p) {
    return (unsigned)__cvta_generic_to_shared(p);
}
__device__ __forceinline__ void cp16(unsigned saddr, const void* g) {
    asm volatile("cp.async.cg.shared.global [%0], [%1], 16;" :: "r"(saddr), "l"(g));
}
__device__ __forceinline__ void cp_commit() {
    asm volatile("cp.async.commit_group;" ::: "memory");
}
__device__ __forceinline__ void ldsm4(unsigned& r0, unsigned& r1, unsigned& r2, unsigned& r3, unsigned addr) {
    asm volatile("ldmatrix.sync.aligned.m8n8.x4.shared.b16 {%0,%1,%2,%3},[%4];"
                 : "=r"(r0), "=r"(r1), "=r"(r2), "=r"(r3) : "r"(addr));
}
__device__ __forceinline__ void ldsm4t(unsigned& r0, unsigned& r1, unsigned& r2, unsigned& r3, unsigned addr) {
    asm volatile("ldmatrix.sync.aligned.m8n8.x4.trans.shared.b16 {%0,%1,%2,%3},[%4];"
                 : "=r"(r0), "=r"(r1), "=r"(r2), "=r"(r3) : "r"(addr));
}
__device__ __forceinline__ void mma16(float* d, const unsigned* a, const unsigned* b, const float* c) {
    asm volatile(
        "mma.sync.aligned.m16n8k16.row.col.f32.f16.f16.f32 "
        "{%0,%1,%2,%3},{%4,%5,%6,%7},{%8,%9},{%10,%11,%12,%13};\n"
        : "=f"(d[0]), "=f"(d[1]), "=f"(d[2]), "=f"(d[3])
        : "r"(a[0]), "r"(a[1]), "r"(a[2]), "r"(a[3]),
          "r"(b[0]), "r"(b[1]),
          "f"(c[0]), "f"(c[1]), "f"(c[2]), "f"(c[3]));
}
__device__ __forceinline__ unsigned pack2(float a, float b) {
    __half2 h = __floats2half2_rn(a, b);
    return *reinterpret_cast<unsigned*>(&h);
}

// ---------------------------------------------------------------------------
// fp16 GEMM: out[m,n] = sum_k A[m,k]*W[n,k] (+bias); M=8192, N=K=768.
// CTA 128x64, k-chunk 64, 256 threads (8 warps 4x2, 32x32 per warp).
// Double-buffered cp.async staging, ldmatrix fragments, HMMA.16816.
// ---------------------------------------------------------------------------
#define GLD 72
template <typename OT>
__global__ __launch_bounds__(256) void gemm_h(
    const __half* __restrict__ A, const __half* __restrict__ W,
    const float* __restrict__ bias, OT* __restrict__ out)
{
    extern __shared__ __half sh[];
    __half* Asm[2] = { sh,                sh + 128 * GLD };
    __half* Bsm[2] = { sh + 256 * GLD,    sh + 256 * GLD + 64 * GLD };

    const int tid = threadIdx.x;
    const int m0 = blockIdx.y * 128, n0 = blockIdx.x * 64;
    const int warp = tid >> 5, lane = tid & 31;
    const int wm = (warp & 3) * 32, wn = (warp >> 2) * 32;
    const int lrA = lane & 15, lcA = (lane >> 4) * 8;

    auto issue = [&](int st, int k0) {
        #pragma unroll
        for (int i = 0; i < 4; i++) {
            int idx = tid + i * 256;               // 1024 chunks
            int row = idx >> 3, col = (idx & 7) * 8;
            cp16(sa(&Asm[st][row * GLD + col]), A + (size_t)(m0 + row) * 768 + k0 + col);
        }
        #pragma unroll
        for (int i = 0; i < 2; i++) {
            int idx = tid + i * 256;               // 512 chunks
            int row = idx >> 3, col = (idx & 7) * 8;
            cp16(sa(&Bsm[st][row * GLD + col]), W + (size_t)(n0 + row) * 768 + k0 + col);
        }
        cp_commit();
    };

    float acc[2][4][4] = {};
    issue(0, 0);

    for (int kc = 0; kc < 12; kc++) {
        if (kc < 11) issue((kc + 1) & 1, (kc + 1) * 64);
        if (kc < 11) asm volatile("cp.async.wait_group 1;" ::: "memory");
        else         asm volatile("cp.async.wait_group 0;" ::: "memory");
        __syncthreads();

        const __half* Ab = Asm[kc & 1];
        const __half* Bb = Bsm[kc & 1];
        #pragma unroll
        for (int kk = 0; kk < 4; kk++) {
            unsigned a[2][4], b[2][4];
            #pragma unroll
            for (int mi = 0; mi < 2; mi++)
                ldsm4(a[mi][0], a[mi][1], a[mi][2], a[mi][3],
                      sa(&Ab[(wm + 16 * mi + lrA) * GLD + kk * 16 + lcA]));
            #pragma unroll
            for (int nh = 0; nh < 2; nh++)
                ldsm4(b[nh][0], b[nh][1], b[nh][2], b[nh][3],
                      sa(&Bb[(wn + 16 * nh + lrA) * GLD + kk * 16 + lcA]));
            #pragma unroll
            for (int mi = 0; mi < 2; mi++)
                #pragma unroll
                for (int nh = 0; nh < 2; nh++) {
                    unsigned bf0[2] = { b[nh][0], b[nh][2] };
                    unsigned bf1[2] = { b[nh][1], b[nh][3] };
                    mma16(acc[mi][2 * nh],     a[mi], bf0, acc[mi][2 * nh]);
                    mma16(acc[mi][2 * nh + 1], a[mi], bf1, acc[mi][2 * nh + 1]);
                }
        }
        __syncthreads();
    }

    const int g = lane >> 2, q = lane & 3;
    #pragma unroll
    for (int ni = 0; ni < 4; ni++) {
        int col = n0 + wn + 8 * ni + 2 * q;
        float b0 = bias ? bias[col]     : 0.f;
        float b1 = bias ? bias[col + 1] : 0.f;
        #pragma unroll
        for (int mi = 0; mi < 2; mi++) {
            int row = m0 + wm + 16 * mi + g;
            if constexpr (sizeof(OT) == 2) {
                *(__half2*)((__half*)out + (size_t)row * 768 + col) =
                    __floats2half2_rn(acc[mi][ni][0] + b0, acc[mi][ni][1] + b1);
                *(__half2*)((__half*)out + (size_t)(row + 8) * 768 + col) =
                    __floats2half2_rn(acc[mi][ni][2] + b0, acc[mi][ni][3] + b1);
            } else {
                float2 v0 = { acc[mi][ni][0] + b0, acc[mi][ni][1] + b1 };
                float2 v1 = { acc[mi][ni][2] + b0, acc[mi][ni][3] + b1 };
                *(float2*)((float*)out + (size_t)row * 768 + col) = v0;
                *(float2*)((float*)out + (size_t)(row + 8) * 768 + col) = v1;
            }
        }
    }
}

// ---------------------------------------------------------------------------
// fp16 flash attention (FA2-style). CTA = 64 q rows, 4 warps x 16 rows.
// kt tile 64, D=64. Q frags in regs for whole loop; P stays in regs
// (C-frag -> A-frag identity for m16n8k16); V via ldmatrix.trans.
// K/V double-buffered with cp.async.
// ---------------------------------------------------------------------------
#define ALD 72
__global__ __launch_bounds__(128) void attn_h(
    const __half* __restrict__ Qg, const __half* __restrict__ Kg,
    const __half* __restrict__ Vg, __half* __restrict__ Og)
{
    extern __shared__ __half sh[];
    __half* Qs    = sh;                                  // 64 x ALD
    __half* Ksm[2] = { sh + 64 * ALD,  sh + 2 * 64 * ALD };
    __half* Vsm[2] = { sh + 3 * 64 * ALD, sh + 4 * 64 * ALD };

    const int tid = threadIdx.x;
    const int warp = tid >> 5, lane = tid & 31;
    const int wm = warp * 16;
    const int qt = blockIdx.x * 64;
    const int h = blockIdx.y, b = blockIdx.z;
    const size_t base = ((size_t)b * T_) * C_ + (size_t)h * D_;

    const int lrA = lane & 15, lcA = (lane >> 4) * 8;
    const int trR = (lane & 7) + ((lane >> 3) & 1) * 8, trC = (lane >> 4) * 8;

    auto issueKV = [&](int st, int kt) {
        #pragma unroll
        for (int i = 0; i < 4; i++) {
            int idx = tid + i * 128;             // 512 chunks each
            int row = idx >> 3, col = (idx & 7) * 8;
            cp16(sa(&Ksm[st][row * ALD + col]), Kg + base + (size_t)(kt + row) * C_ + col);
            cp16(sa(&Vsm[st][row * ALD + col]), Vg + base + (size_t)(kt + row) * C_ + col);
        }
        cp_commit();
    };

    // Q + first KV tile
    {
        #pragma unroll
        for (int i = 0; i < 4; i++) {
            int idx = tid + i * 128;
            int row = idx >> 3, col = (idx & 7) * 8;
            cp16(sa(&Qs[row * ALD + col]), Qg + base + (size_t)(qt + row) * C_ + col);
        }
        // commit together with tile 0
        #pragma unroll
        for (int i = 0; i < 4; i++) {
            int idx = tid + i * 128;
            int row = idx >> 3, col = (idx & 7) * 8;
            cp16(sa(&Ksm[0][row * ALD + col]), Kg + base + (size_t)row * C_ + col);
            cp16(sa(&Vsm[0][row * ALD + col]), Vg + base + (size_t)row * C_ + col);
        }
        cp_commit();
    }

    unsigned qa[4][4];
    float m0r = -1e30f, m1r = -1e30f, l0 = 0.f, l1 = 0.f;
    float ofr[8][4] = {};

    for (int kti = 0; kti < 32; kti++) {
        if (kti < 31) issueKV((kti + 1) & 1, (kti + 1) * 64);
        if (kti < 31) asm volatile("cp.async.wait_group 1;" ::: "memory");
        else          asm volatile("cp.async.wait_group 0;" ::: "memory");
        __syncthreads();

        if (kti == 0) {
            const __half2 s2 = __floats2half2_rn(0.125f, 0.125f);
            #pragma unroll
            for (int kj = 0; kj < 4; kj++) {
                ldsm4(qa[kj][0], qa[kj][1], qa[kj][2], qa[kj][3],
                      sa(&Qs[(wm + lrA) * ALD + kj * 16 + lcA]));
                #pragma unroll
                for (int r = 0; r < 4; r++) {
                    __half2 hv = *reinterpret_cast<__half2*>(&qa[kj][r]);
                    hv = __hmul2(hv, s2);
                    qa[kj][r] = *reinterpret_cast<unsigned*>(&hv);
                }
            }
        }

        const __half* Kb = Ksm[kti & 1];
        const __half* Vb = Vsm[kti & 1];

        // S = Q @ K^T  (16 x 64 per warp)
        float sfr[8][4] = {};
        #pragma unroll
        for (int kj = 0; kj < 4; kj++) {
            #pragma unroll
            for (int nb = 0; nb < 4; nb++) {
                unsigned u0, u1, u2, u3;
                ldsm4(u0, u1, u2, u3, sa(&Kb[(16 * nb + lrA) * ALD + kj * 16 + lcA]));
                unsigned bf0[2] = { u0, u2 }, bf1[2] = { u1, u3 };
                mma16(sfr[2 * nb],     qa[kj], bf0, sfr[2 * nb]);
                mma16(sfr[2 * nb + 1], qa[kj], bf1, sfr[2 * nb + 1]);
            }
        }

        // online softmax (thread holds rows wm+g / wm+g+8)
        float mx0 = -1e30f, mx1 = -1e30f;
        #pragma unroll
        for (int ni = 0; ni < 8; ni++) {
            mx0 = fmaxf(mx0, fmaxf(sfr[ni][0], sfr[ni][1]));
            mx1 = fmaxf(mx1, fmaxf(sfr[ni][2], sfr[ni][3]));
        }
        #pragma unroll
        for (int off = 1; off <= 2; off <<= 1) {
            mx0 = fmaxf(mx0, __shfl_xor_sync(0xffffffffu, mx0, off));
            mx1 = fmaxf(mx1, __shfl_xor_sync(0xffffffffu, mx1, off));
        }
        float mn0 = fmaxf(m0r, mx0), mn1 = fmaxf(m1r, mx1);
        float al0 = __expf(m0r - mn0), al1 = __expf(m1r - mn1);
        m0r = mn0; m1r = mn1;
        float s0 = 0.f, s1 = 0.f;
        #pragma unroll
        for (int ni = 0; ni < 8; ni++) {
            sfr[ni][0] = __expf(sfr[ni][0] - mn0);
            sfr[ni][1] = __expf(sfr[ni][1] - mn0);
            sfr[ni][2] = __expf(sfr[ni][2] - mn1);
            sfr[ni][3] = __expf(sfr[ni][3] - mn1);
            s0 += sfr[ni][0] + sfr[ni][1];
            s1 += sfr[ni][2] + sfr[ni][3];
        }
        #pragma unroll
        for (int off = 1; off <= 2; off <<= 1) {
            s0 += __shfl_xor_sync(0xffffffffu, s0, off);
            s1 += __shfl_xor_sync(0xffffffffu, s1, off);
        }
        l0 = l0 * al0 + s0;
        l1 = l1 * al1 + s1;
        #pragma unroll
        for (int ni = 0; ni < 8; ni++) {
            ofr[ni][0] *= al0; ofr[ni][1] *= al0;
            ofr[ni][2] *= al1; ofr[ni][3] *= al1;
        }

        // P C-frags -> A-frags (register-only)
        unsigned pa[4][4];
        #pragma unroll
        for (int kj2 = 0; kj2 < 4; kj2++) {
            pa[kj2][0] = pack2(sfr[2 * kj2][0],     sfr[2 * kj2][1]);
            pa[kj2][1] = pack2(sfr[2 * kj2][2],     sfr[2 * kj2][3]);
            pa[kj2][2] = pack2(sfr[2 * kj2 + 1][0], sfr[2 * kj2 + 1][1]);
            pa[kj2][3] = pack2(sfr[2 * kj2 + 1][2], sfr[2 * kj2 + 1][3]);
        }

        // O += P @ V   (V^T fragments via ldmatrix.trans)
        #pragma unroll
        for (int kj2 = 0; kj2 < 4; kj2++) {
            #pragma unroll
            for (int db = 0; db < 4; db++) {
                unsigned u0, u1, u2, u3;
                ldsm4t(u0, u1, u2, u3, sa(&Vb[(16 * kj2 + trR) * ALD + 16 * db + trC]));
                unsigned bf0[2] = { u0, u1 }, bf1[2] = { u2, u3 };
                mma16(ofr[2 * db],     pa[kj2], bf0, ofr[2 * db]);
                mma16(ofr[2 * db + 1], pa[kj2], bf1, ofr[2 * db + 1]);
            }
        }
        __syncthreads();
    }

    const int g = lane >> 2, q = lane & 3;
    float inv0 = 1.0f / l0, inv1 = 1.0f / l1;
    #pragma unroll
    for (int ni = 0; ni < 8; ni++) {
        int col = 8 * ni + 2 * q;
        *(__half2*)((__half*)Og + base + (size_t)(qt + wm + g) * C_ + col) =
            __floats2half2_rn(ofr[ni][0] * inv0, ofr[ni][1] * inv0);
        *(__half2*)((__half*)Og + base + (size_t)(qt + wm + g + 8) * C_ + col) =
            __floats2half2_rn(ofr[ni][2] * inv1, ofr[ni][3] * inv1);
    }
}

// ---------------------------------------------------------------------------
extern "C" void kernel_launch(void* const* d_in, const int* in_sizes, int n_in,
                              void* d_out, int out_size)
{
    const float* x  = (const float*)d_in[0];
    const float* Wq = (const float*)d_in[1];
    const float* bq = (const float*)d_in[2];
    const float* Wk = (const float*)d_in[3];
    const float* bk = (const float*)d_in[4];
    const float* Wv = (const float*)d_in[5];
    const float* bv = (const float*)d_in[6];
    const float* Wp = (const float*)d_in[7];
    float* out = (float*)d_out;

    __half *xh, *wq, *wk, *wv, *wp, *qh, *kh, *vh, *ah;
    cudaGetSymbolAddress((void**)&xh, g_xh);
    cudaGetSymbolAddress((void**)&wq, g_wq);
    cudaGetSymbolAddress((void**)&wk, g_wk);
    cudaGetSymbolAddress((void**)&wv, g_wv);
    cudaGetSymbolAddress((void**)&wp, g_wp);
    cudaGetSymbolAddress((void**)&qh, g_qh);
    cudaGetSymbolAddress((void**)&kh, g_kh);
    cudaGetSymbolAddress((void**)&vh, g_vh);
    cudaGetSymbolAddress((void**)&ah, g_ah);

    // fp32 -> fp16 conversions
    {
        int n4 = M_TOT * C_ / 4;
        f2h_kernel<<<(n4 + 255) / 256, 256>>>(x, xh, n4);
        int w4 = C_ * C_ / 4;
        f2h_kernel<<<(w4 + 255) / 256, 256>>>(Wq, wq, w4);
        f2h_kernel<<<(w4 + 255) / 256, 256>>>(Wk, wk, w4);
        f2h_kernel<<<(w4 + 255) / 256, 256>>>(Wv, wv, w4);
        f2h_kernel<<<(w4 + 255) / 256, 256>>>(Wp, wp, w4);
    }

    const int gemm_smem = (256 + 128) * GLD * (int)sizeof(__half);  // 55296
    cudaFuncSetAttribute(gemm_h<__half>,
                         cudaFuncAttributeMaxDynamicSharedMemorySize, gemm_smem);
    cudaFuncSetAttribute(gemm_h<float>,
                         cudaFuncAttributeMaxDynamicSharedMemorySize, gemm_smem);

    dim3 ggrid(C_ / 64, M_TOT / 128);
    gemm_h<__half><<<ggrid, 256, gemm_smem>>>(xh, wq, bq, qh);
    gemm_h<__half><<<ggrid, 256, gemm_smem>>>(xh, wk, bk, kh);
    gemm_h<__half><<<ggrid, 256, gemm_smem>>>(xh, wv, bv, vh);

    const int attn_smem = 5 * 64 * ALD * (int)sizeof(__half);       // 46080
    attn_h<<<dim3(T_ / 64, H_, B_), 128, attn_smem>>>(qh, kh, vh, ah);

    gemm_h<float><<<ggrid, 256, gemm_smem>>>(ah, wp, nullptr, out);
}

// round 5
// speedup vs baseline: 7.1863x; 1.1013x over previous
#include <cuda_runtime.h>
#include <cuda_fp16.h>

#define B_ 4
#define T_ 2048
#define C_ 768
#define H_ 12
#define D_ 64
#define M_TOT (B_ * T_)

// fp16 scratch (allocation-guard-safe device globals)
__device__ __half g_xh[M_TOT * C_];
__device__ __half g_wq[C_ * C_], g_wk[C_ * C_], g_wv[C_ * C_], g_wp[C_ * C_];
__device__ __half g_qh[M_TOT * C_], g_kh[M_TOT * C_], g_vh[M_TOT * C_], g_ah[M_TOT * C_];

// ---------------------------------------------------------------------------
__global__ void f2h_kernel(const float* __restrict__ in, __half* __restrict__ out, int n4)
{
    int i = blockIdx.x * blockDim.x + threadIdx.x;
    if (i < n4) {
        float4 v = ((const float4*)in)[i];
        ((__half2*)out)[2 * i]     = __floats2half2_rn(v.x, v.y);
        ((__half2*)out)[2 * i + 1] = __floats2half2_rn(v.z, v.w);
    }
}

// ---------------------------------------------------------------------------
__device__ __forceinline__ unsigned sa(const void* p) {
    return (unsigned)__cvta_generic_to_shared(p);
}
__device__ __forceinline__ void cp16(unsigned saddr, const void* g) {
    asm volatile("cp.async.cg.shared.global [%0], [%1], 16;" :: "r"(saddr), "l"(g));
}
__device__ __forceinline__ void cp_commit() {
    asm volatile("cp.async.commit_group;" ::: "memory");
}
__device__ __forceinline__ void ldsm4(unsigned& r0, unsigned& r1, unsigned& r2, unsigned& r3, unsigned addr) {
    asm volatile("ldmatrix.sync.aligned.m8n8.x4.shared.b16 {%0,%1,%2,%3},[%4];"
                 : "=r"(r0), "=r"(r1), "=r"(r2), "=r"(r3) : "r"(addr));
}
__device__ __forceinline__ void ldsm4t(unsigned& r0, unsigned& r1, unsigned& r2, unsigned& r3, unsigned addr) {
    asm volatile("ldmatrix.sync.aligned.m8n8.x4.trans.shared.b16 {%0,%1,%2,%3},[%4];"
                 : "=r"(r0), "=r"(r1), "=r"(r2), "=r"(r3) : "r"(addr));
}
__device__ __forceinline__ void mma16(float* d, const unsigned* a, const unsigned* b, const float* c) {
    asm volatile(
        "mma.sync.aligned.m16n8k16.row.col.f32.f16.f16.f32 "
        "{%0,%1,%2,%3},{%4,%5,%6,%7},{%8,%9},{%10,%11,%12,%13};\n"
        : "=f"(d[0]), "=f"(d[1]), "=f"(d[2]), "=f"(d[3])
        : "r"(a[0]), "r"(a[1]), "r"(a[2]), "r"(a[3]),
          "r"(b[0]), "r"(b[1]),
          "f"(c[0]), "f"(c[1]), "f"(c[2]), "f"(c[3]));
}
__device__ __forceinline__ unsigned pack2(float a, float b) {
    __half2 h = __floats2half2_rn(a, b);
    return *reinterpret_cast<unsigned*>(&h);
}

#define GLD 72

// ---------------------------------------------------------------------------
// Fused QKV GEMM: one CTA computes a 128x64 tile for ALL THREE projections,
// loading each A (=x) tile once. 256 threads, k-chunk 64, 2-stage cp.async.
// ---------------------------------------------------------------------------
__global__ __launch_bounds__(256) void gemm_qkv(
    const __half* __restrict__ A,
    const __half* __restrict__ W0, const __half* __restrict__ W1, const __half* __restrict__ W2,
    const float* __restrict__ b0, const float* __restrict__ b1, const float* __restrict__ b2,
    __half* __restrict__ o0, __half* __restrict__ o1, __half* __restrict__ o2)
{
    extern __shared__ __half sh[];
    __half* Asm[2] = { sh, sh + 128 * GLD };
    __half* Bbase  = sh + 256 * GLD;   // [st][w][64*GLD]

    const int tid = threadIdx.x;
    const int m0 = blockIdx.y * 128, n0 = blockIdx.x * 64;
    const int warp = tid >> 5, lane = tid & 31;
    const int wm = (warp & 3) * 32, wn = (warp >> 2) * 32;
    const int lrA = lane & 15, lcA = (lane >> 4) * 8;
    const __half* Ws[3] = { W0, W1, W2 };

    auto issue = [&](int st, int k0) {
        #pragma unroll
        for (int i = 0; i < 4; i++) {
            int idx = tid + i * 256;
            int row = idx >> 3, col = (idx & 7) * 8;
            cp16(sa(&Asm[st][row * GLD + col]), A + (size_t)(m0 + row) * 768 + k0 + col);
        }
        #pragma unroll
        for (int w = 0; w < 3; w++) {
            __half* Bs = Bbase + (st * 3 + w) * 64 * GLD;
            #pragma unroll
            for (int i = 0; i < 2; i++) {
                int idx = tid + i * 256;
                int row = idx >> 3, col = (idx & 7) * 8;
                cp16(sa(&Bs[row * GLD + col]), Ws[w] + (size_t)(n0 + row) * 768 + k0 + col);
            }
        }
        cp_commit();
    };

    float acc[3][2][4][4] = {};
    issue(0, 0);

    for (int kc = 0; kc < 12; kc++) {
        if (kc < 11) { issue((kc + 1) & 1, (kc + 1) * 64);
                       asm volatile("cp.async.wait_group 1;" ::: "memory"); }
        else           asm volatile("cp.async.wait_group 0;" ::: "memory");
        __syncthreads();

        const __half* Ab = Asm[kc & 1];
        #pragma unroll
        for (int kk = 0; kk < 4; kk++) {
            unsigned a[2][4];
            #pragma unroll
            for (int mi = 0; mi < 2; mi++)
                ldsm4(a[mi][0], a[mi][1], a[mi][2], a[mi][3],
                      sa(&Ab[(wm + 16 * mi + lrA) * GLD + kk * 16 + lcA]));
            #pragma unroll
            for (int w = 0; w < 3; w++) {
                const __half* Bb = Bbase + ((kc & 1) * 3 + w) * 64 * GLD;
                unsigned b[2][4];
                #pragma unroll
                for (int nh = 0; nh < 2; nh++)
                    ldsm4(b[nh][0], b[nh][1], b[nh][2], b[nh][3],
                          sa(&Bb[(wn + 16 * nh + lrA) * GLD + kk * 16 + lcA]));
                #pragma unroll
                for (int mi = 0; mi < 2; mi++)
                    #pragma unroll
                    for (int nh = 0; nh < 2; nh++) {
                        unsigned bf0[2] = { b[nh][0], b[nh][2] };
                        unsigned bf1[2] = { b[nh][1], b[nh][3] };
                        mma16(acc[w][mi][2 * nh],     a[mi], bf0, acc[w][mi][2 * nh]);
                        mma16(acc[w][mi][2 * nh + 1], a[mi], bf1, acc[w][mi][2 * nh + 1]);
                    }
            }
        }
        __syncthreads();
    }

    const int g = lane >> 2, q = lane & 3;
    const float* bs[3] = { b0, b1, b2 };
    __half* os[3] = { o0, o1, o2 };
    #pragma unroll
    for (int w = 0; w < 3; w++) {
        #pragma unroll
        for (int ni = 0; ni < 4; ni++) {
            int col = n0 + wn + 8 * ni + 2 * q;
            float c0 = bs[w][col], c1 = bs[w][col + 1];
            #pragma unroll
            for (int mi = 0; mi < 2; mi++) {
                int row = m0 + wm + 16 * mi + g;
                *(__half2*)(os[w] + (size_t)row * 768 + col) =
                    __floats2half2_rn(acc[w][mi][ni][0] + c0, acc[w][mi][ni][1] + c1);
                *(__half2*)(os[w] + (size_t)(row + 8) * 768 + col) =
                    __floats2half2_rn(acc[w][mi][ni][2] + c0, acc[w][mi][ni][3] + c1);
            }
        }
    }
}

// ---------------------------------------------------------------------------
// Output projection GEMM (fp16 in, fp32 out), as in R4.
// ---------------------------------------------------------------------------
__global__ __launch_bounds__(256) void gemm_proj(
    const __half* __restrict__ A, const __half* __restrict__ W,
    float* __restrict__ out)
{
    extern __shared__ __half sh[];
    __half* Asm[2] = { sh,             sh + 128 * GLD };
    __half* Bsm[2] = { sh + 256 * GLD, sh + 256 * GLD + 64 * GLD };

    const int tid = threadIdx.x;
    const int m0 = blockIdx.y * 128, n0 = blockIdx.x * 64;
    const int warp = tid >> 5, lane = tid & 31;
    const int wm = (warp & 3) * 32, wn = (warp >> 2) * 32;
    const int lrA = lane & 15, lcA = (lane >> 4) * 8;

    auto issue = [&](int st, int k0) {
        #pragma unroll
        for (int i = 0; i < 4; i++) {
            int idx = tid + i * 256;
            int row = idx >> 3, col = (idx & 7) * 8;
            cp16(sa(&Asm[st][row * GLD + col]), A + (size_t)(m0 + row) * 768 + k0 + col);
        }
        #pragma unroll
        for (int i = 0; i < 2; i++) {
            int idx = tid + i * 256;
            int row = idx >> 3, col = (idx & 7) * 8;
            cp16(sa(&Bsm[st][row * GLD + col]), W + (size_t)(n0 + row) * 768 + k0 + col);
        }
        cp_commit();
    };

    float acc[2][4][4] = {};
    issue(0, 0);

    for (int kc = 0; kc < 12; kc++) {
        if (kc < 11) { issue((kc + 1) & 1, (kc + 1) * 64);
                       asm volatile("cp.async.wait_group 1;" ::: "memory"); }
        else           asm volatile("cp.async.wait_group 0;" ::: "memory");
        __syncthreads();

        const __half* Ab = Asm[kc & 1];
        const __half* Bb = Bsm[kc & 1];
        #pragma unroll
        for (int kk = 0; kk < 4; kk++) {
            unsigned a[2][4], b[2][4];
            #pragma unroll
            for (int mi = 0; mi < 2; mi++)
                ldsm4(a[mi][0], a[mi][1], a[mi][2], a[mi][3],
                      sa(&Ab[(wm + 16 * mi + lrA) * GLD + kk * 16 + lcA]));
            #pragma unroll
            for (int nh = 0; nh < 2; nh++)
                ldsm4(b[nh][0], b[nh][1], b[nh][2], b[nh][3],
                      sa(&Bb[(wn + 16 * nh + lrA) * GLD + kk * 16 + lcA]));
            #pragma unroll
            for (int mi = 0; mi < 2; mi++)
                #pragma unroll
                for (int nh = 0; nh < 2; nh++) {
                    unsigned bf0[2] = { b[nh][0], b[nh][2] };
                    unsigned bf1[2] = { b[nh][1], b[nh][3] };
                    mma16(acc[mi][2 * nh],     a[mi], bf0, acc[mi][2 * nh]);
                    mma16(acc[mi][2 * nh + 1], a[mi], bf1, acc[mi][2 * nh + 1]);
                }
        }
        __syncthreads();
    }

    const int g = lane >> 2, q = lane & 3;
    #pragma unroll
    for (int ni = 0; ni < 4; ni++) {
        int col = n0 + wn + 8 * ni + 2 * q;
        #pragma unroll
        for (int mi = 0; mi < 2; mi++) {
            int row = m0 + wm + 16 * mi + g;
            float2 v0 = { acc[mi][ni][0], acc[mi][ni][1] };
            float2 v1 = { acc[mi][ni][2], acc[mi][ni][3] };
            *(float2*)(out + (size_t)row * 768 + col) = v0;
            *(float2*)(out + (size_t)(row + 8) * 768 + col) = v1;
        }
    }
}

// ---------------------------------------------------------------------------
// fp16 flash attention. CTA = 128 q rows, 8 warps x 16 rows. kt tile 64.
// 3-stage cp.async pipeline, ONE __syncthreads per iteration.
// ---------------------------------------------------------------------------
#define ALD 72
__global__ __launch_bounds__(256, 2) void attn_h(
    const __half* __restrict__ Qg, const __half* __restrict__ Kg,
    const __half* __restrict__ Vg, __half* __restrict__ Og)
{
    extern __shared__ __half sh[];
    __half* Qs = sh;                       // 128 x ALD
    __half* Kst = sh + 128 * ALD;          // 3 stages x 64 x ALD
    __half* Vst = sh + (128 + 3 * 64) * ALD;

    const int tid = threadIdx.x;
    const int warp = tid >> 5, lane = tid & 31;
    const int wm = warp * 16;
    const int qt = blockIdx.x * 128;
    const int h = blockIdx.y, b = blockIdx.z;
    const size_t base = ((size_t)b * T_) * C_ + (size_t)h * D_;

    const int lrA = lane & 15, lcA = (lane >> 4) * 8;
    const int trR = (lane & 7) + ((lane >> 3) & 1) * 8, trC = (lane >> 4) * 8;

    auto issueKV = [&](int st, int kt) {
        __half* Ks = Kst + st * 64 * ALD;
        __half* Vs = Vst + st * 64 * ALD;
        #pragma unroll
        for (int i = 0; i < 2; i++) {
            int idx = tid + i * 256;            // 512 chunks each
            int row = idx >> 3, col = (idx & 7) * 8;
            cp16(sa(&Ks[row * ALD + col]), Kg + base + (size_t)(kt + row) * C_ + col);
            cp16(sa(&Vs[row * ALD + col]), Vg + base + (size_t)(kt + row) * C_ + col);
        }
        cp_commit();
    };

    // Q (1024 chunks) + tile 0 in one group, tile 1 in a second group.
    {
        #pragma unroll
        for (int i = 0; i < 4; i++) {
            int idx = tid + i * 256;
            int row = idx >> 3, col = (idx & 7) * 8;
            cp16(sa(&Qs[row * ALD + col]), Qg + base + (size_t)(qt + row) * C_ + col);
        }
        #pragma unroll
        for (int i = 0; i < 2; i++) {
            int idx = tid + i * 256;
            int row = idx >> 3, col = (idx & 7) * 8;
            cp16(sa(&Kst[row * ALD + col]), Kg + base + (size_t)row * C_ + col);
            cp16(sa(&Vst[row * ALD + col]), Vg + base + (size_t)row * C_ + col);
        }
        cp_commit();
        issueKV(1, 64);
    }

    unsigned qa[4][4];
    float m0r = -1e30f, m1r = -1e30f, l0 = 0.f, l1 = 0.f;
    float ofr[8][4] = {};

    for (int kti = 0; kti < 32; kti++) {
        if (kti < 31) asm volatile("cp.async.wait_group 1;" ::: "memory");
        else          asm volatile("cp.async.wait_group 0;" ::: "memory");
        __syncthreads();
        if (kti < 30) issueKV((kti + 2) % 3, (kti + 2) * 64);

        if (kti == 0) {
            const __half2 s2 = __floats2half2_rn(0.125f, 0.125f);
            #pragma unroll
            for (int kj = 0; kj < 4; kj++) {
                ldsm4(qa[kj][0], qa[kj][1], qa[kj][2], qa[kj][3],
                      sa(&Qs[(wm + lrA) * ALD + kj * 16 + lcA]));
                #pragma unroll
                for (int r = 0; r < 4; r++) {
                    __half2 hv = *reinterpret_cast<__half2*>(&qa[kj][r]);
                    hv = __hmul2(hv, s2);
                    qa[kj][r] = *reinterpret_cast<unsigned*>(&hv);
                }
            }
        }

        const __half* Kb = Kst + (kti % 3) * 64 * ALD;
        const __half* Vb = Vst + (kti % 3) * 64 * ALD;

        // S = Q @ K^T
        float sfr[8][4] = {};
        #pragma unroll
        for (int kj = 0; kj < 4; kj++) {
            #pragma unroll
            for (int nb = 0; nb < 4; nb++) {
                unsigned u0, u1, u2, u3;
                ldsm4(u0, u1, u2, u3, sa(&Kb[(16 * nb + lrA) * ALD + kj * 16 + lcA]));
                unsigned bf0[2] = { u0, u2 }, bf1[2] = { u1, u3 };
                mma16(sfr[2 * nb],     qa[kj], bf0, sfr[2 * nb]);
                mma16(sfr[2 * nb + 1], qa[kj], bf1, sfr[2 * nb + 1]);
            }
        }

        // online softmax
        float mx0 = -1e30f, mx1 = -1e30f;
        #pragma unroll
        for (int ni = 0; ni < 8; ni++) {
            mx0 = fmaxf(mx0, fmaxf(sfr[ni][0], sfr[ni][1]));
            mx1 = fmaxf(mx1, fmaxf(sfr[ni][2], sfr[ni][3]));
        }
        #pragma unroll
        for (int off = 1; off <= 2; off <<= 1) {
            mx0 = fmaxf(mx0, __shfl_xor_sync(0xffffffffu, mx0, off));
            mx1 = fmaxf(mx1, __shfl_xor_sync(0xffffffffu, mx1, off));
        }
        float mn0 = fmaxf(m0r, mx0), mn1 = fmaxf(m1r, mx1);
        float al0 = __expf(m0r - mn0), al1 = __expf(m1r - mn1);
        m0r = mn0; m1r = mn1;
        float s0 = 0.f, s1 = 0.f;
        #pragma unroll
        for (int ni = 0; ni < 8; ni++) {
            sfr[ni][0] = __expf(sfr[ni][0] - mn0);
            sfr[ni][1] = __expf(sfr[ni][1] - mn0);
            sfr[ni][2] = __expf(sfr[ni][2] - mn1);
            sfr[ni][3] = __expf(sfr[ni][3] - mn1);
            s0 += sfr[ni][0] + sfr[ni][1];
            s1 += sfr[ni][2] + sfr[ni][3];
        }
        #pragma unroll
        for (int off = 1; off <= 2; off <<= 1) {
            s0 += __shfl_xor_sync(0xffffffffu, s0, off);
            s1 += __shfl_xor_sync(0xffffffffu, s1, off);
        }
        l0 = l0 * al0 + s0;
        l1 = l1 * al1 + s1;
        #pragma unroll
        for (int ni = 0; ni < 8; ni++) {
            ofr[ni][0] *= al0; ofr[ni][1] *= al0;
            ofr[ni][2] *= al1; ofr[ni][3] *= al1;
        }

        // P C-frags -> A-frags (registers only)
        unsigned pa[4][4];
        #pragma unroll
        for (int kj2 = 0; kj2 < 4; kj2++) {
            pa[kj2][0] = pack2(sfr[2 * kj2][0],     sfr[2 * kj2][1]);
            pa[kj2][1] = pack2(sfr[2 * kj2][2],     sfr[2 * kj2][3]);
            pa[kj2][2] = pack2(sfr[2 * kj2 + 1][0], sfr[2 * kj2 + 1][1]);
            pa[kj2][3] = pack2(sfr[2 * kj2 + 1][2], sfr[2 * kj2 + 1][3]);
        }

        // O += P @ V
        #pragma unroll
        for (int kj2 = 0; kj2 < 4; kj2++) {
            #pragma unroll
            for (int db = 0; db < 4; db++) {
                unsigned u0, u1, u2, u3;
                ldsm4t(u0, u1, u2, u3, sa(&Vb[(16 * kj2 + trR) * ALD + 16 * db + trC]));
                unsigned bf0[2] = { u0, u1 }, bf1[2] = { u2, u3 };
                mma16(ofr[2 * db],     pa[kj2], bf0, ofr[2 * db]);
                mma16(ofr[2 * db + 1], pa[kj2], bf1, ofr[2 * db + 1]);
            }
        }
    }

    const int g = lane >> 2, q = lane & 3;
    float inv0 = 1.0f / l0, inv1 = 1.0f / l1;
    #pragma unroll
    for (int ni = 0; ni < 8; ni++) {
        int col = 8 * ni + 2 * q;
        *(__half2*)((__half*)Og + base + (size_t)(qt + wm + g) * C_ + col) =
            __floats2half2_rn(ofr[ni][0] * inv0, ofr[ni][1] * inv0);
        *(__half2*)((__half*)Og + base + (size_t)(qt + wm + g + 8) * C_ + col) =
            __floats2half2_rn(ofr[ni][2] * inv1, ofr[ni][3] * inv1);
    }
}

// ---------------------------------------------------------------------------
extern "C" void kernel_launch(void* const* d_in, const int* in_sizes, int n_in,
                              void* d_out, int out_size)
{
    const float* x  = (const float*)d_in[0];
    const float* Wq = (const float*)d_in[1];
    const float* bq = (const float*)d_in[2];
    const float* Wk = (const float*)d_in[3];
    const float* bk = (const float*)d_in[4];
    const float* Wv = (const float*)d_in[5];
    const float* bv = (const float*)d_in[6];
    const float* Wp = (const float*)d_in[7];
    float* out = (float*)d_out;

    __half *xh, *wq, *wk, *wv, *wp, *qh, *kh, *vh, *ah;
    cudaGetSymbolAddress((void**)&xh, g_xh);
    cudaGetSymbolAddress((void**)&wq, g_wq);
    cudaGetSymbolAddress((void**)&wk, g_wk);
    cudaGetSymbolAddress((void**)&wv, g_wv);
    cudaGetSymbolAddress((void**)&wp, g_wp);
    cudaGetSymbolAddress((void**)&qh, g_qh);
    cudaGetSymbolAddress((void**)&kh, g_kh);
    cudaGetSymbolAddress((void**)&vh, g_vh);
    cudaGetSymbolAddress((void**)&ah, g_ah);

    {
        int n4 = M_TOT * C_ / 4;
        f2h_kernel<<<(n4 + 255) / 256, 256>>>(x, xh, n4);
        int w4 = C_ * C_ / 4;
        f2h_kernel<<<(w4 + 255) / 256, 256>>>(Wq, wq, w4);
        f2h_kernel<<<(w4 + 255) / 256, 256>>>(Wk, wk, w4);
        f2h_kernel<<<(w4 + 255) / 256, 256>>>(Wv, wv, w4);
        f2h_kernel<<<(w4 + 255) / 256, 256>>>(Wp, wp, w4);
    }

    const int qkv_smem = (256 + 384) * GLD * (int)sizeof(__half);   // 92160
    cudaFuncSetAttribute(gemm_qkv,
                         cudaFuncAttributeMaxDynamicSharedMemorySize, qkv_smem);
    gemm_qkv<<<dim3(C_ / 64, M_TOT / 128), 256, qkv_smem>>>(
        xh, wq, wk, wv, bq, bk, bv, qh, kh, vh);

    const int attn_smem = (128 + 6 * 64) * ALD * (int)sizeof(__half); // 73728
    cudaFuncSetAttribute(attn_h,
                         cudaFuncAttributeMaxDynamicSharedMemorySize, attn_smem);
    attn_h<<<dim3(T_ / 128, H_, B_), 256, attn_smem>>>(qh, kh, vh, ah);

    const int proj_smem = (256 + 128) * GLD * (int)sizeof(__half);  // 55296
    cudaFuncSetAttribute(gemm_proj,
                         cudaFuncAttributeMaxDynamicSharedMemorySize, proj_smem);
    gemm_proj<<<dim3(C_ / 64, M_TOT / 128), 256, proj_smem>>>(ah, wp, out);
}

// round 7
// speedup vs baseline: 7.3975x; 1.0294x over previous
#include <cuda_runtime.h>
#include <cuda_fp16.h>

#define B_ 4
#define T_ 2048
#define C_ 768
#define H_ 12
#define D_ 64
#define M_TOT (B_ * T_)

// fp16 scratch (allocation-guard-safe device globals)
__device__ __half g_xh[M_TOT * C_];
__device__ __half g_wq[C_ * C_], g_wk[C_ * C_], g_wv[C_ * C_], g_wp[C_ * C_];
__device__ __half g_qh[M_TOT * C_], g_kh[M_TOT * C_], g_vh[M_TOT * C_], g_ah[M_TOT * C_];

// ---------------------------------------------------------------------------
__global__ void f2h_kernel(const float* __restrict__ in, __half* __restrict__ out, int n4)
{
    int i = blockIdx.x * blockDim.x + threadIdx.x;
    if (i < n4) {
        float4 v = ((const float4*)in)[i];
        ((__half2*)out)[2 * i]     = __floats2half2_rn(v.x, v.y);
        ((__half2*)out)[2 * i + 1] = __floats2half2_rn(v.z, v.w);
    }
}

// ---------------------------------------------------------------------------
__device__ __forceinline__ unsigned sa(const void* p) {
    return (unsigned)__cvta_generic_to_shared(p);
}
__device__ __forceinline__ void cp16(unsigned saddr, const void* g) {
    asm volatile("cp.async.cg.shared.global [%0], [%1], 16;" :: "r"(saddr), "l"(g));
}
__device__ __forceinline__ void cp_commit() {
    asm volatile("cp.async.commit_group;" ::: "memory");
}
__device__ __forceinline__ void ldsm4(unsigned& r0, unsigned& r1, unsigned& r2, unsigned& r3, unsigned addr) {
    asm volatile("ldmatrix.sync.aligned.m8n8.x4.shared.b16 {%0,%1,%2,%3},[%4];"
                 : "=r"(r0), "=r"(r1), "=r"(r2), "=r"(r3) : "r"(addr));
}
__device__ __forceinline__ void ldsm4t(unsigned& r0, unsigned& r1, unsigned& r2, unsigned& r3, unsigned addr) {
    asm volatile("ldmatrix.sync.aligned.m8n8.x4.trans.shared.b16 {%0,%1,%2,%3},[%4];"
                 : "=r"(r0), "=r"(r1), "=r"(r2), "=r"(r3) : "r"(addr));
}
__device__ __forceinline__ void mma16(float* d, const unsigned* a, const unsigned* b, const float* c) {
    asm volatile(
        "mma.sync.aligned.m16n8k16.row.col.f32.f16.f16.f32 "
        "{%0,%1,%2,%3},{%4,%5,%6,%7},{%8,%9},{%10,%11,%12,%13};\n"
        : "=f"(d[0]), "=f"(d[1]), "=f"(d[2]), "=f"(d[3])
        : "r"(a[0]), "r"(a[1]), "r"(a[2]), "r"(a[3]),
          "r"(b[0]), "r"(b[1]),
          "f"(c[0]), "f"(c[1]), "f"(c[2]), "f"(c[3]));
}
__device__ __forceinline__ unsigned pack2(float a, float b) {
    __half2 h = __floats2half2_rn(a, b);
    return *reinterpret_cast<unsigned*>(&h);
}

#define GLD 72

// ---------------------------------------------------------------------------
// Fused QKV GEMM: one CTA computes a 128x64 tile for ALL THREE projections,
// loading each A (=x) tile once. 256 threads, k-chunk 64, 2-stage cp.async.
// ---------------------------------------------------------------------------
__global__ __launch_bounds__(256) void gemm_qkv(
    const __half* __restrict__ A,
    const __half* __restrict__ W0, const __half* __restrict__ W1, const __half* __restrict__ W2,
    const float* __restrict__ b0, const float* __restrict__ b1, const float* __restrict__ b2,
    __half* __restrict__ o0, __half* __restrict__ o1, __half* __restrict__ o2)
{
    extern __shared__ __half sh[];
    __half* Asm[2] = { sh, sh + 128 * GLD };
    __half* Bbase  = sh + 256 * GLD;   // [st][w][64*GLD]

    const int tid = threadIdx.x;
    const int m0 = blockIdx.y * 128, n0 = blockIdx.x * 64;
    const int warp = tid >> 5, lane = tid & 31;
    const int wm = (warp & 3) * 32, wn = (warp >> 2) * 32;
    const int lrA = lane & 15, lcA = (lane >> 4) * 8;
    const __half* Ws[3] = { W0, W1, W2 };

    auto issue = [&](int st, int k0) {
        #pragma unroll
        for (int i = 0; i < 4; i++) {
            int idx = tid + i * 256;
            int row = idx >> 3, col = (idx & 7) * 8;
            cp16(sa(&Asm[st][row * GLD + col]), A + (size_t)(m0 + row) * 768 + k0 + col);
        }
        #pragma unroll
        for (int w = 0; w < 3; w++) {
            __half* Bs = Bbase + (st * 3 + w) * 64 * GLD;
            #pragma unroll
            for (int i = 0; i < 2; i++) {
                int idx = tid + i * 256;
                int row = idx >> 3, col = (idx & 7) * 8;
                cp16(sa(&Bs[row * GLD + col]), Ws[w] + (size_t)(n0 + row) * 768 + k0 + col);
            }
        }
        cp_commit();
    };

    float acc[3][2][4][4] = {};
    issue(0, 0);

    for (int kc = 0; kc < 12; kc++) {
        if (kc < 11) { issue((kc + 1) & 1, (kc + 1) * 64);
                       asm volatile("cp.async.wait_group 1;" ::: "memory"); }
        else           asm volatile("cp.async.wait_group 0;" ::: "memory");
        __syncthreads();

        const __half* Ab = Asm[kc & 1];
        #pragma unroll
        for (int kk = 0; kk < 4; kk++) {
            unsigned a[2][4];
            #pragma unroll
            for (int mi = 0; mi < 2; mi++)
                ldsm4(a[mi][0], a[mi][1], a[mi][2], a[mi][3],
                      sa(&Ab[(wm + 16 * mi + lrA) * GLD + kk * 16 + lcA]));
            #pragma unroll
            for (int w = 0; w < 3; w++) {
                const __half* Bb = Bbase + ((kc & 1) * 3 + w) * 64 * GLD;
                unsigned b[2][4];
                #pragma unroll
                for (int nh = 0; nh < 2; nh++)
                    ldsm4(b[nh][0], b[nh][1], b[nh][2], b[nh][3],
                          sa(&Bb[(wn + 16 * nh + lrA) * GLD + kk * 16 + lcA]));
                #pragma unroll
                for (int mi = 0; mi < 2; mi++)
                    #pragma unroll
                    for (int nh = 0; nh < 2; nh++) {
                        unsigned bf0[2] = { b[nh][0], b[nh][2] };
                        unsigned bf1[2] = { b[nh][1], b[nh][3] };
                        mma16(acc[w][mi][2 * nh],     a[mi], bf0, acc[w][mi][2 * nh]);
                        mma16(acc[w][mi][2 * nh + 1], a[mi], bf1, acc[w][mi][2 * nh + 1]);
                    }
            }
        }
        __syncthreads();
    }

    const int g = lane >> 2, q = lane & 3;
    const float* bs[3] = { b0, b1, b2 };
    __half* os[3] = { o0, o1, o2 };
    #pragma unroll
    for (int w = 0; w < 3; w++) {
        #pragma unroll
        for (int ni = 0; ni < 4; ni++) {
            int col = n0 + wn + 8 * ni + 2 * q;
            float c0 = bs[w][col], c1 = bs[w][col + 1];
            #pragma unroll
            for (int mi = 0; mi < 2; mi++) {
                int row = m0 + wm + 16 * mi + g;
                *(__half2*)(os[w] + (size_t)row * 768 + col) =
                    __floats2half2_rn(acc[w][mi][ni][0] + c0, acc[w][mi][ni][1] + c1);
                *(__half2*)(os[w] + (size_t)(row + 8) * 768 + col) =
                    __floats2half2_rn(acc[w][mi][ni][2] + c0, acc[w][mi][ni][3] + c1);
            }
        }
    }
}

// ---------------------------------------------------------------------------
// Output projection GEMM (fp16 in, fp32 out). CTA tile 128x128, 8 warps
// (4m x 2n), warp tile 32x64, k-chunk 64, 2-stage cp.async.
// ---------------------------------------------------------------------------
__global__ __launch_bounds__(256) void gemm_proj(
    const __half* __restrict__ A, const __half* __restrict__ W,
    float* __restrict__ out)
{
    extern __shared__ __half sh[];
    __half* Asm[2] = { sh,             sh + 128 * GLD };
    __half* Bsm[2] = { sh + 256 * GLD, sh + 384 * GLD };

    const int tid = threadIdx.x;
    const int m0 = blockIdx.y * 128, n0 = blockIdx.x * 128;
    const int warp = tid >> 5, lane = tid & 31;
    const int wm = (warp & 3) * 32, wn = (warp >> 2) * 64;
    const int lrA = lane & 15, lcA = (lane >> 4) * 8;

    auto issue = [&](int st, int k0) {
        #pragma unroll
        for (int i = 0; i < 4; i++) {
            int idx = tid + i * 256;
            int row = idx >> 3, col = (idx & 7) * 8;
            cp16(sa(&Asm[st][row * GLD + col]), A + (size_t)(m0 + row) * 768 + k0 + col);
            cp16(sa(&Bsm[st][row * GLD + col]), W + (size_t)(n0 + row) * 768 + k0 + col);
        }
        cp_commit();
    };

    float acc[2][8][4] = {};
    issue(0, 0);

    for (int kc = 0; kc < 12; kc++) {
        if (kc < 11) { issue((kc + 1) & 1, (kc + 1) * 64);
                       asm volatile("cp.async.wait_group 1;" ::: "memory"); }
        else           asm volatile("cp.async.wait_group 0;" ::: "memory");
        __syncthreads();

        const __half* Ab = Asm[kc & 1];
        const __half* Bb = Bsm[kc & 1];
        #pragma unroll
        for (int kk = 0; kk < 4; kk++) {
            unsigned a[2][4], b[4][4];
            #pragma unroll
            for (int mi = 0; mi < 2; mi++)
                ldsm4(a[mi][0], a[mi][1], a[mi][2], a[mi][3],
                      sa(&Ab[(wm + 16 * mi + lrA) * GLD + kk * 16 + lcA]));
            #pragma unroll
            for (int nh = 0; nh < 4; nh++)
                ldsm4(b[nh][0], b[nh][1], b[nh][2], b[nh][3],
                      sa(&Bb[(wn + 16 * nh + lrA) * GLD + kk * 16 + lcA]));
            #pragma unroll
            for (int mi = 0; mi < 2; mi++)
                #pragma unroll
                for (int nh = 0; nh < 4; nh++) {
                    unsigned bf0[2] = { b[nh][0], b[nh][2] };
                    unsigned bf1[2] = { b[nh][1], b[nh][3] };
                    mma16(acc[mi][2 * nh],     a[mi], bf0, acc[mi][2 * nh]);
                    mma16(acc[mi][2 * nh + 1], a[mi], bf1, acc[mi][2 * nh + 1]);
                }
        }
        __syncthreads();
    }

    const int g = lane >> 2, q = lane & 3;
    #pragma unroll
    for (int ni = 0; ni < 8; ni++) {
        int col = n0 + wn + 8 * ni + 2 * q;
        #pragma unroll
        for (int mi = 0; mi < 2; mi++) {
            int row = m0 + wm + 16 * mi + g;
            float2 v0 = { acc[mi][ni][0], acc[mi][ni][1] };
            float2 v1 = { acc[mi][ni][2], acc[mi][ni][3] };
            *(float2*)(out + (size_t)row * 768 + col) = v0;
            *(float2*)(out + (size_t)(row + 8) * 768 + col) = v1;
        }
    }
}

// ---------------------------------------------------------------------------
// fp16 flash attention. CTA = 128 q rows, 8 warps x 16 rows. kt tile 64.
// 3-stage cp.async pipeline, ONE __syncthreads per iteration.
// Softmax in exp2 domain (log2e folded into Q scale).
// ---------------------------------------------------------------------------
#define ALD 72
__global__ __launch_bounds__(256, 2) void attn_h(
    const __half* __restrict__ Qg, const __half* __restrict__ Kg,
    const __half* __restrict__ Vg, __half* __restrict__ Og)
{
    extern __shared__ __half sh[];
    __half* Qs = sh;                       // 128 x ALD
    __half* Kst = sh + 128 * ALD;          // 3 stages x 64 x ALD
    __half* Vst = sh + (128 + 3 * 64) * ALD;

    const int tid = threadIdx.x;
    const int warp = tid >> 5, lane = tid & 31;
    const int wm = warp * 16;
    const int qt = blockIdx.x * 128;
    const int h = blockIdx.y, b = blockIdx.z;
    const size_t base = ((size_t)b * T_) * C_ + (size_t)h * D_;

    const int lrA = lane & 15, lcA = (lane >> 4) * 8;
    const int trR = (lane & 7) + ((lane >> 3) & 1) * 8, trC = (lane >> 4) * 8;

    auto issueKV = [&](int st, int kt) {
        __half* Ks = Kst + st * 64 * ALD;
        __half* Vs = Vst + st * 64 * ALD;
        #pragma unroll
        for (int i = 0; i < 2; i++) {
            int idx = tid + i * 256;
            int row = idx >> 3, col = (idx & 7) * 8;
            cp16(sa(&Ks[row * ALD + col]), Kg + base + (size_t)(kt + row) * C_ + col);
            cp16(sa(&Vs[row * ALD + col]), Vg + base + (size_t)(kt + row) * C_ + col);
        }
        cp_commit();
    };

    {
        #pragma unroll
        for (int i = 0; i < 4; i++) {
            int idx = tid + i * 256;
            int row = idx >> 3, col = (idx & 7) * 8;
            cp16(sa(&Qs[row * ALD + col]), Qg + base + (size_t)(qt + row) * C_ + col);
        }
        #pragma unroll
        for (int i = 0; i < 2; i++) {
            int idx = tid + i * 256;
            int row = idx >> 3, col = (idx & 7) * 8;
            cp16(sa(&Kst[row * ALD + col]), Kg + base + (size_t)row * C_ + col);
            cp16(sa(&Vst[row * ALD + col]), Vg + base + (size_t)row * C_ + col);
        }
        cp_commit();
        issueKV(1, 64);
    }

    unsigned qa[4][4];
    float m0r = -1e30f, m1r = -1e30f, l0 = 0.f, l1 = 0.f;
    float ofr[8][4] = {};

    for (int kti = 0; kti < 32; kti++) {
        if (kti < 31) asm volatile("cp.async.wait_group 1;" ::: "memory");
        else          asm volatile("cp.async.wait_group 0;" ::: "memory");
        __syncthreads();
        if (kti < 30) issueKV((kti + 2) % 3, (kti + 2) * 64);

        if (kti == 0) {
            // 0.125 * log2(e): scores land in log2 domain -> bare EX2 later
            const __half2 s2 = __floats2half2_rn(0.180336880f, 0.180336880f);
            #pragma unroll
            for (int kj = 0; kj < 4; kj++) {
                ldsm4(qa[kj][0], qa[kj][1], qa[kj][2], qa[kj][3],
                      sa(&Qs[(wm + lrA) * ALD + kj * 16 + lcA]));
                #pragma unroll
                for (int r = 0; r < 4; r++) {
                    __half2 hv = *reinterpret_cast<__half2*>(&qa[kj][r]);
                    hv = __hmul2(hv, s2);
                    qa[kj][r] = *reinterpret_cast<unsigned*>(&hv);
                }
            }
        }

        const __half* Kb = Kst + (kti % 3) * 64 * ALD;
        const __half* Vb = Vst + (kti % 3) * 64 * ALD;

        // S = Q @ K^T (log2 domain)
        float sfr[8][4] = {};
        #pragma unroll
        for (int kj = 0; kj < 4; kj++) {
            #pragma unroll
            for (int nb = 0; nb < 4; nb++) {
                unsigned u0, u1, u2, u3;
                ldsm4(u0, u1, u2, u3, sa(&Kb[(16 * nb + lrA) * ALD + kj * 16 + lcA]));
                unsigned bf0[2] = { u0, u2 }, bf1[2] = { u1, u3 };
                mma16(sfr[2 * nb],     qa[kj], bf0, sfr[2 * nb]);
                mma16(sfr[2 * nb + 1], qa[kj], bf1, sfr[2 * nb + 1]);
            }
        }

        // online softmax (base-2)
        float mx0 = -1e30f, mx1 = -1e30f;
        #pragma unroll
        for (int ni = 0; ni < 8; ni++) {
            mx0 = fmaxf(mx0, fmaxf(sfr[ni][0], sfr[ni][1]));
            mx1 = fmaxf(mx1, fmaxf(sfr[ni][2], sfr[ni][3]));
        }
        #pragma unroll
        for (int off = 1; off <= 2; off <<= 1) {
            mx0 = fmaxf(mx0, __shfl_xor_sync(0xffffffffu, mx0, off));
            mx1 = fmaxf(mx1, __shfl_xor_sync(0xffffffffu, mx1, off));
        }
        float mn0 = fmaxf(m0r, mx0), mn1 = fmaxf(m1r, mx1);
        float al0 = exp2f(m0r - mn0), al1 = exp2f(m1r - mn1);
        m0r = mn0; m1r = mn1;
        float s0 = 0.f, s1 = 0.f;
        #pragma unroll
        for (int ni = 0; ni < 8; ni++) {
            sfr[ni][0] = exp2f(sfr[ni][0] - mn0);
            sfr[ni][1] = exp2f(sfr[ni][1] - mn0);
            sfr[ni][2] = exp2f(sfr[ni][2] - mn1);
            sfr[ni][3] = exp2f(sfr[ni][3] - mn1);
            s0 += sfr[ni][0] + sfr[ni][1];
            s1 += sfr[ni][2] + sfr[ni][3];
        }
        #pragma unroll
        for (int off = 1; off <= 2; off <<= 1) {
            s0 += __shfl_xor_sync(0xffffffffu, s0, off);
            s1 += __shfl_xor_sync(0xffffffffu, s1, off);
        }
        l0 = l0 * al0 + s0;
        l1 = l1 * al1 + s1;
        #pragma unroll
        for (int ni = 0; ni < 8; ni++) {
            ofr[ni][0] *= al0; ofr[ni][1] *= al0;
            ofr[ni][2] *= al1; ofr[ni][3] *= al1;
        }

        // P C-frags -> A-frags (registers only)
        unsigned pa[4][4];
        #pragma unroll
        for (int kj2 = 0; kj2 < 4; kj2++) {
            pa[kj2][0] = pack2(sfr[2 * kj2][0],     sfr[2 * kj2][1]);
            pa[kj2][1] = pack2(sfr[2 * kj2][2],     sfr[2 * kj2][3]);
            pa[kj2][2] = pack2(sfr[2 * kj2 + 1][0], sfr[2 * kj2 + 1][1]);
            pa[kj2][3] = pack2(sfr[2 * kj2 + 1][2], sfr[2 * kj2 + 1][3]);
        }

        // O += P @ V
        #pragma unroll
        for (int kj2 = 0; kj2 < 4; kj2++) {
            #pragma unroll
            for (int db = 0; db < 4; db++) {
                unsigned u0, u1, u2, u3;
                ldsm4t(u0, u1, u2, u3, sa(&Vb[(16 * kj2 + trR) * ALD + 16 * db + trC]));
                unsigned bf0[2] = { u0, u1 }, bf1[2] = { u2, u3 };
                mma16(ofr[2 * db],     pa[kj2], bf0, ofr[2 * db]);
                mma16(ofr[2 * db + 1], pa[kj2], bf1, ofr[2 * db + 1]);
            }
        }
    }

    const int g = lane >> 2, q = lane & 3;
    float inv0 = 1.0f / l0, inv1 = 1.0f / l1;
    #pragma unroll
    for (int ni = 0; ni < 8; ni++) {
        int col = 8 * ni + 2 * q;
        *(__half2*)((__half*)Og + base + (size_t)(qt + wm + g) * C_ + col) =
            __floats2half2_rn(ofr[ni][0] * inv0, ofr[ni][1] * inv0);
        *(__half2*)((__half*)Og + base + (size_t)(qt + wm + g + 8) * C_ + col) =
            __floats2half2_rn(ofr[ni][2] * inv1, ofr[ni][3] * inv1);
    }
}

// ---------------------------------------------------------------------------
extern "C" void kernel_launch(void* const* d_in, const int* in_sizes, int n_in,
                              void* d_out, int out_size)
{
    const float* x  = (const float*)d_in[0];
    const float* Wq = (const float*)d_in[1];
    const float* bq = (const float*)d_in[2];
    const float* Wk = (const float*)d_in[3];
    const float* bk = (const float*)d_in[4];
    const float* Wv = (const float*)d_in[5];
    const float* bv = (const float*)d_in[6];
    const float* Wp = (const float*)d_in[7];
    float* out = (float*)d_out;

    __half *xh, *wq, *wk, *wv, *wp, *qh, *kh, *vh, *ah;
    cudaGetSymbolAddress((void**)&xh, g_xh);
    cudaGetSymbolAddress((void**)&wq, g_wq);
    cudaGetSymbolAddress((void**)&wk, g_wk);
    cudaGetSymbolAddress((void**)&wv, g_wv);
    cudaGetSymbolAddress((void**)&wp, g_wp);
    cudaGetSymbolAddress((void**)&qh, g_qh);
    cudaGetSymbolAddress((void**)&kh, g_kh);
    cudaGetSymbolAddress((void**)&vh, g_vh);
    cudaGetSymbolAddress((void**)&ah, g_ah);

    {
        int n4 = M_TOT * C_ / 4;
        f2h_kernel<<<(n4 + 255) / 256, 256>>>(x, xh, n4);
        int w4 = C_ * C_ / 4;
        f2h_kernel<<<(w4 + 255) / 256, 256>>>(Wq, wq, w4);
        f2h_kernel<<<(w4 + 255) / 256, 256>>>(Wk, wk, w4);
        f2h_kernel<<<(w4 + 255) / 256, 256>>>(Wv, wv, w4);
        f2h_kernel<<<(w4 + 255) / 256, 256>>>(Wp, wp, w4);
    }

    const int qkv_smem = (256 + 384) * GLD * (int)sizeof(__half);   // 92160
    cudaFuncSetAttribute(gemm_qkv,
                         cudaFuncAttributeMaxDynamicSharedMemorySize, qkv_smem);
    gemm_qkv<<<dim3(C_ / 64, M_TOT / 128), 256, qkv_smem>>>(
        xh, wq, wk, wv, bq, bk, bv, qh, kh, vh);

    const int attn_smem = (128 + 6 * 64) * ALD * (int)sizeof(__half); // 73728
    cudaFuncSetAttribute(attn_h,
                         cudaFuncAttributeMaxDynamicSharedMemorySize, attn_smem);
    attn_h<<<dim3(T_ / 128, H_, B_), 256, attn_smem>>>(qh, kh, vh, ah);

    const int proj_smem = (256 + 256) * GLD * (int)sizeof(__half);  // 73728
    cudaFuncSetAttribute(gemm_proj,
                         cudaFuncAttributeMaxDynamicSharedMemorySize, proj_smem);
    gemm_proj<<<dim3(C_ / 128, M_TOT / 128), 256, proj_smem>>>(ah, wp, out);
}

// round 8
// speedup vs baseline: 7.5953x; 1.0267x over previous
#include <cuda_runtime.h>
#include <cuda_fp16.h>

#define B_ 4
#define T_ 2048
#define C_ 768
#define H_ 12
#define D_ 64
#define M_TOT (B_ * T_)

// fp16 scratch (allocation-guard-safe device globals)
__device__ __half g_xh[M_TOT * C_];
__device__ __half g_wq[C_ * C_], g_wk[C_ * C_], g_wv[C_ * C_], g_wp[C_ * C_];
__device__ __half g_qh[M_TOT * C_], g_kh[M_TOT * C_], g_vh[M_TOT * C_], g_ah[M_TOT * C_];

// ---------------------------------------------------------------------------
// One fused fp32->fp16 conversion kernel for x + 4 weight matrices.
// Region layout (in float4 units): x: 393216, then 4 x 147456.
// ---------------------------------------------------------------------------
#define X4   (M_TOT * C_ / 4)
#define W4   (C_ * C_ / 4)
__global__ void f2h_all(
    const float* __restrict__ x,  const float* __restrict__ wq,
    const float* __restrict__ wk, const float* __restrict__ wv,
    const float* __restrict__ wp,
    __half* __restrict__ xh, __half* __restrict__ oq, __half* __restrict__ ok,
    __half* __restrict__ ov, __half* __restrict__ op)
{
    int i = blockIdx.x * blockDim.x + threadIdx.x;
    const float* src; __half* dst; int off;
    if      (i < X4)             { src = x;  dst = xh; off = i; }
    else if (i < X4 + W4)        { src = wq; dst = oq; off = i - X4; }
    else if (i < X4 + 2 * W4)    { src = wk; dst = ok; off = i - X4 - W4; }
    else if (i < X4 + 3 * W4)    { src = wv; dst = ov; off = i - X4 - 2 * W4; }
    else if (i < X4 + 4 * W4)    { src = wp; dst = op; off = i - X4 - 3 * W4; }
    else return;
    float4 v = ((const float4*)src)[off];
    ((__half2*)dst)[2 * off]     = __floats2half2_rn(v.x, v.y);
    ((__half2*)dst)[2 * off + 1] = __floats2half2_rn(v.z, v.w);
}

// ---------------------------------------------------------------------------
__device__ __forceinline__ unsigned sa(const void* p) {
    return (unsigned)__cvta_generic_to_shared(p);
}
__device__ __forceinline__ void cp16(unsigned saddr, const void* g) {
    asm volatile("cp.async.cg.shared.global [%0], [%1], 16;" :: "r"(saddr), "l"(g));
}
__device__ __forceinline__ void cp_commit() {
    asm volatile("cp.async.commit_group;" ::: "memory");
}
__device__ __forceinline__ void ldsm4(unsigned& r0, unsigned& r1, unsigned& r2, unsigned& r3, unsigned addr) {
    asm volatile("ldmatrix.sync.aligned.m8n8.x4.shared.b16 {%0,%1,%2,%3},[%4];"
                 : "=r"(r0), "=r"(r1), "=r"(r2), "=r"(r3) : "r"(addr));
}
__device__ __forceinline__ void ldsm4t(unsigned& r0, unsigned& r1, unsigned& r2, unsigned& r3, unsigned addr) {
    asm volatile("ldmatrix.sync.aligned.m8n8.x4.trans.shared.b16 {%0,%1,%2,%3},[%4];"
                 : "=r"(r0), "=r"(r1), "=r"(r2), "=r"(r3) : "r"(addr));
}
__device__ __forceinline__ void mma16(float* d, const unsigned* a, const unsigned* b, const float* c) {
    asm volatile(
        "mma.sync.aligned.m16n8k16.row.col.f32.f16.f16.f32 "
        "{%0,%1,%2,%3},{%4,%5,%6,%7},{%8,%9},{%10,%11,%12,%13};\n"
        : "=f"(d[0]), "=f"(d[1]), "=f"(d[2]), "=f"(d[3])
        : "r"(a[0]), "r"(a[1]), "r"(a[2]), "r"(a[3]),
          "r"(b[0]), "r"(b[1]),
          "f"(c[0]), "f"(c[1]), "f"(c[2]), "f"(c[3]));
}
__device__ __forceinline__ unsigned pack2(float a, float b) {
    __half2 h = __floats2half2_rn(a, b);
    return *reinterpret_cast<unsigned*>(&h);
}

#define GLD 72

// ---------------------------------------------------------------------------
// Fused QKV GEMM: one CTA computes a 128x64 tile for ALL THREE projections,
// loading each A (=x) tile once. 256 threads, k-chunk 64, 2-stage cp.async.
// ---------------------------------------------------------------------------
__global__ __launch_bounds__(256) void gemm_qkv(
    const __half* __restrict__ A,
    const __half* __restrict__ W0, const __half* __restrict__ W1, const __half* __restrict__ W2,
    const float* __restrict__ b0, const float* __restrict__ b1, const float* __restrict__ b2,
    __half* __restrict__ o0, __half* __restrict__ o1, __half* __restrict__ o2)
{
    extern __shared__ __half sh[];
    __half* Asm[2] = { sh, sh + 128 * GLD };
    __half* Bbase  = sh + 256 * GLD;   // [st][w][64*GLD]

    const int tid = threadIdx.x;
    const int m0 = blockIdx.y * 128, n0 = blockIdx.x * 64;
    const int warp = tid >> 5, lane = tid & 31;
    const int wm = (warp & 3) * 32, wn = (warp >> 2) * 32;
    const int lrA = lane & 15, lcA = (lane >> 4) * 8;
    const __half* Ws[3] = { W0, W1, W2 };

    auto issue = [&](int st, int k0) {
        #pragma unroll
        for (int i = 0; i < 4; i++) {
            int idx = tid + i * 256;
            int row = idx >> 3, col = (idx & 7) * 8;
            cp16(sa(&Asm[st][row * GLD + col]), A + (size_t)(m0 + row) * 768 + k0 + col);
        }
        #pragma unroll
        for (int w = 0; w < 3; w++) {
            __half* Bs = Bbase + (st * 3 + w) * 64 * GLD;
            #pragma unroll
            for (int i = 0; i < 2; i++) {
                int idx = tid + i * 256;
                int row = idx >> 3, col = (idx & 7) * 8;
                cp16(sa(&Bs[row * GLD + col]), Ws[w] + (size_t)(n0 + row) * 768 + k0 + col);
            }
        }
        cp_commit();
    };

    float acc[3][2][4][4] = {};
    issue(0, 0);

    for (int kc = 0; kc < 12; kc++) {
        if (kc < 11) { issue((kc + 1) & 1, (kc + 1) * 64);
                       asm volatile("cp.async.wait_group 1;" ::: "memory"); }
        else           asm volatile("cp.async.wait_group 0;" ::: "memory");
        __syncthreads();

        const __half* Ab = Asm[kc & 1];
        #pragma unroll
        for (int kk = 0; kk < 4; kk++) {
            unsigned a[2][4];
            #pragma unroll
            for (int mi = 0; mi < 2; mi++)
                ldsm4(a[mi][0], a[mi][1], a[mi][2], a[mi][3],
                      sa(&Ab[(wm + 16 * mi + lrA) * GLD + kk * 16 + lcA]));
            #pragma unroll
            for (int w = 0; w < 3; w++) {
                const __half* Bb = Bbase + ((kc & 1) * 3 + w) * 64 * GLD;
                unsigned b[2][4];
                #pragma unroll
                for (int nh = 0; nh < 2; nh++)
                    ldsm4(b[nh][0], b[nh][1], b[nh][2], b[nh][3],
                          sa(&Bb[(wn + 16 * nh + lrA) * GLD + kk * 16 + lcA]));
                #pragma unroll
                for (int mi = 0; mi < 2; mi++)
                    #pragma unroll
                    for (int nh = 0; nh < 2; nh++) {
                        unsigned bf0[2] = { b[nh][0], b[nh][2] };
                        unsigned bf1[2] = { b[nh][1], b[nh][3] };
                        mma16(acc[w][mi][2 * nh],     a[mi], bf0, acc[w][mi][2 * nh]);
                        mma16(acc[w][mi][2 * nh + 1], a[mi], bf1, acc[w][mi][2 * nh + 1]);
                    }
            }
        }
        __syncthreads();
    }

    const int g = lane >> 2, q = lane & 3;
    const float* bs[3] = { b0, b1, b2 };
    __half* os[3] = { o0, o1, o2 };
    #pragma unroll
    for (int w = 0; w < 3; w++) {
        #pragma unroll
        for (int ni = 0; ni < 4; ni++) {
            int col = n0 + wn + 8 * ni + 2 * q;
            float c0 = bs[w][col], c1 = bs[w][col + 1];
            #pragma unroll
            for (int mi = 0; mi < 2; mi++) {
                int row = m0 + wm + 16 * mi + g;
                *(__half2*)(os[w] + (size_t)row * 768 + col) =
                    __floats2half2_rn(acc[w][mi][ni][0] + c0, acc[w][mi][ni][1] + c1);
                *(__half2*)(os[w] + (size_t)(row + 8) * 768 + col) =
                    __floats2half2_rn(acc[w][mi][ni][2] + c0, acc[w][mi][ni][3] + c1);
            }
        }
    }
}

// ---------------------------------------------------------------------------
// Output projection GEMM (fp16 in, fp32 out). CTA tile 128x128, 8 warps
// (4m x 2n), warp tile 32x64, k-chunk 64, 2-stage cp.async, 2 CTAs/SM.
// ---------------------------------------------------------------------------
__global__ __launch_bounds__(256, 2) void gemm_proj(
    const __half* __restrict__ A, const __half* __restrict__ W,
    float* __restrict__ out)
{
    extern __shared__ __half sh[];
    __half* Asm[2] = { sh,             sh + 128 * GLD };
    __half* Bsm[2] = { sh + 256 * GLD, sh + 384 * GLD };

    const int tid = threadIdx.x;
    const int m0 = blockIdx.y * 128, n0 = blockIdx.x * 128;
    const int warp = tid >> 5, lane = tid & 31;
    const int wm = (warp & 3) * 32, wn = (warp >> 2) * 64;
    const int lrA = lane & 15, lcA = (lane >> 4) * 8;

    auto issue = [&](int st, int k0) {
        #pragma unroll
        for (int i = 0; i < 4; i++) {
            int idx = tid + i * 256;
            int row = idx >> 3, col = (idx & 7) * 8;
            cp16(sa(&Asm[st][row * GLD + col]), A + (size_t)(m0 + row) * 768 + k0 + col);
            cp16(sa(&Bsm[st][row * GLD + col]), W + (size_t)(n0 + row) * 768 + k0 + col);
        }
        cp_commit();
    };

    float acc[2][8][4] = {};
    issue(0, 0);

    for (int kc = 0; kc < 12; kc++) {
        if (kc < 11) { issue((kc + 1) & 1, (kc + 1) * 64);
                       asm volatile("cp.async.wait_group 1;" ::: "memory"); }
        else           asm volatile("cp.async.wait_group 0;" ::: "memory");
        __syncthreads();

        const __half* Ab = Asm[kc & 1];
        const __half* Bb = Bsm[kc & 1];
        #pragma unroll
        for (int kk = 0; kk < 4; kk++) {
            unsigned a[2][4], b[4][4];
            #pragma unroll
            for (int mi = 0; mi < 2; mi++)
                ldsm4(a[mi][0], a[mi][1], a[mi][2], a[mi][3],
                      sa(&Ab[(wm + 16 * mi + lrA) * GLD + kk * 16 + lcA]));
            #pragma unroll
            for (int nh = 0; nh < 4; nh++)
                ldsm4(b[nh][0], b[nh][1], b[nh][2], b[nh][3],
                      sa(&Bb[(wn + 16 * nh + lrA) * GLD + kk * 16 + lcA]));
            #pragma unroll
            for (int mi = 0; mi < 2; mi++)
                #pragma unroll
                for (int nh = 0; nh < 4; nh++) {
                    unsigned bf0[2] = { b[nh][0], b[nh][2] };
                    unsigned bf1[2] = { b[nh][1], b[nh][3] };
                    mma16(acc[mi][2 * nh],     a[mi], bf0, acc[mi][2 * nh]);
                    mma16(acc[mi][2 * nh + 1], a[mi], bf1, acc[mi][2 * nh + 1]);
                }
        }
        __syncthreads();
    }

    const int g = lane >> 2, q = lane & 3;
    #pragma unroll
    for (int ni = 0; ni < 8; ni++) {
        int col = n0 + wn + 8 * ni + 2 * q;
        #pragma unroll
        for (int mi = 0; mi < 2; mi++) {
            int row = m0 + wm + 16 * mi + g;
            float2 v0 = { acc[mi][ni][0], acc[mi][ni][1] };
            float2 v1 = { acc[mi][ni][2], acc[mi][ni][3] };
            *(float2*)(out + (size_t)row * 768 + col) = v0;
            *(float2*)(out + (size_t)(row + 8) * 768 + col) = v1;
        }
    }
}

// ---------------------------------------------------------------------------
// fp16 flash attention. CTA = 128 q rows, 8 warps x 16 rows. kt tile 64.
// 3-stage cp.async pipeline, ONE __syncthreads per iteration.
// Softmax in exp2 domain (log2e folded into Q scale).
// ---------------------------------------------------------------------------
#define ALD 72
__global__ __launch_bounds__(256, 2) void attn_h(
    const __half* __restrict__ Qg, const __half* __restrict__ Kg,
    const __half* __restrict__ Vg, __half* __restrict__ Og)
{
    extern __shared__ __half sh[];
    __half* Qs = sh;                       // 128 x ALD
    __half* Kst = sh + 128 * ALD;          // 3 stages x 64 x ALD
    __half* Vst = sh + (128 + 3 * 64) * ALD;

    const int tid = threadIdx.x;
    const int warp = tid >> 5, lane = tid & 31;
    const int wm = warp * 16;
    const int qt = blockIdx.x * 128;
    const int h = blockIdx.y, b = blockIdx.z;
    const size_t base = ((size_t)b * T_) * C_ + (size_t)h * D_;

    const int lrA = lane & 15, lcA = (lane >> 4) * 8;
    const int trR = (lane & 7) + ((lane >> 3) & 1) * 8, trC = (lane >> 4) * 8;

    auto issueKV = [&](int st, int kt) {
        __half* Ks = Kst + st * 64 * ALD;
        __half* Vs = Vst + st * 64 * ALD;
        #pragma unroll
        for (int i = 0; i < 2; i++) {
            int idx = tid + i * 256;
            int row = idx >> 3, col = (idx & 7) * 8;
            cp16(sa(&Ks[row * ALD + col]), Kg + base + (size_t)(kt + row) * C_ + col);
            cp16(sa(&Vs[row * ALD + col]), Vg + base + (size_t)(kt + row) * C_ + col);
        }
        cp_commit();
    };

    {
        #pragma unroll
        for (int i = 0; i < 4; i++) {
            int idx = tid + i * 256;
            int row = idx >> 3, col = (idx & 7) * 8;
            cp16(sa(&Qs[row * ALD + col]), Qg + base + (size_t)(qt + row) * C_ + col);
        }
        #pragma unroll
        for (int i = 0; i < 2; i++) {
            int idx = tid + i * 256;
            int row = idx >> 3, col = (idx & 7) * 8;
            cp16(sa(&Kst[row * ALD + col]), Kg + base + (size_t)row * C_ + col);
            cp16(sa(&Vst[row * ALD + col]), Vg + base + (size_t)row * C_ + col);
        }
        cp_commit();
        issueKV(1, 64);
    }

    unsigned qa[4][4];
    float m0r = -1e30f, m1r = -1e30f, l0 = 0.f, l1 = 0.f;
    float ofr[8][4] = {};

    for (int kti = 0; kti < 32; kti++) {
        if (kti < 31) asm volatile("cp.async.wait_group 1;" ::: "memory");
        else          asm volatile("cp.async.wait_group 0;" ::: "memory");
        __syncthreads();
        if (kti < 30) issueKV((kti + 2) % 3, (kti + 2) * 64);

        if (kti == 0) {
            // 0.125 * log2(e): scores land in log2 domain -> bare EX2 later
            const __half2 s2 = __floats2half2_rn(0.180336880f, 0.180336880f);
            #pragma unroll
            for (int kj = 0; kj < 4; kj++) {
                ldsm4(qa[kj][0], qa[kj][1], qa[kj][2], qa[kj][3],
                      sa(&Qs[(wm + lrA) * ALD + kj * 16 + lcA]));
                #pragma unroll
                for (int r = 0; r < 4; r++) {
                    __half2 hv = *reinterpret_cast<__half2*>(&qa[kj][r]);
                    hv = __hmul2(hv, s2);
                    qa[kj][r] = *reinterpret_cast<unsigned*>(&hv);
                }
            }
        }

        const __half* Kb = Kst + (kti % 3) * 64 * ALD;
        const __half* Vb = Vst + (kti % 3) * 64 * ALD;

        // S = Q @ K^T (log2 domain)
        float sfr[8][4] = {};
        #pragma unroll
        for (int kj = 0; kj < 4; kj++) {
            #pragma unroll
            for (int nb = 0; nb < 4; nb++) {
                unsigned u0, u1, u2, u3;
                ldsm4(u0, u1, u2, u3, sa(&Kb[(16 * nb + lrA) * ALD + kj * 16 + lcA]));
                unsigned bf0[2] = { u0, u2 }, bf1[2] = { u1, u3 };
                mma16(sfr[2 * nb],     qa[kj], bf0, sfr[2 * nb]);
                mma16(sfr[2 * nb + 1], qa[kj], bf1, sfr[2 * nb + 1]);
            }
        }

        // online softmax (base-2)
        float mx0 = -1e30f, mx1 = -1e30f;
        #pragma unroll
        for (int ni = 0; ni < 8; ni++) {
            mx0 = fmaxf(mx0, fmaxf(sfr[ni][0], sfr[ni][1]));
            mx1 = fmaxf(mx1, fmaxf(sfr[ni][2], sfr[ni][3]));
        }
        #pragma unroll
        for (int off = 1; off <= 2; off <<= 1) {
            mx0 = fmaxf(mx0, __shfl_xor_sync(0xffffffffu, mx0, off));
            mx1 = fmaxf(mx1, __shfl_xor_sync(0xffffffffu, mx1, off));
        }
        float mn0 = fmaxf(m0r, mx0), mn1 = fmaxf(m1r, mx1);
        float al0 = exp2f(m0r - mn0), al1 = exp2f(m1r - mn1);
        m0r = mn0; m1r = mn1;
        float s0 = 0.f, s1 = 0.f;
        #pragma unroll
        for (int ni = 0; ni < 8; ni++) {
            sfr[ni][0] = exp2f(sfr[ni][0] - mn0);
            sfr[ni][1] = exp2f(sfr[ni][1] - mn0);
            sfr[ni][2] = exp2f(sfr[ni][2] - mn1);
            sfr[ni][3] = exp2f(sfr[ni][3] - mn1);
            s0 += sfr[ni][0] + sfr[ni][1];
            s1 += sfr[ni][2] + sfr[ni][3];
        }
        #pragma unroll
        for (int off = 1; off <= 2; off <<= 1) {
            s0 += __shfl_xor_sync(0xffffffffu, s0, off);
            s1 += __shfl_xor_sync(0xffffffffu, s1, off);
        }
        l0 = l0 * al0 + s0;
        l1 = l1 * al1 + s1;
        #pragma unroll
        for (int ni = 0; ni < 8; ni++) {
            ofr[ni][0] *= al0; ofr[ni][1] *= al0;
            ofr[ni][2] *= al1; ofr[ni][3] *= al1;
        }

        // P C-frags -> A-frags (registers only)
        unsigned pa[4][4];
        #pragma unroll
        for (int kj2 = 0; kj2 < 4; kj2++) {
            pa[kj2][0] = pack2(sfr[2 * kj2][0],     sfr[2 * kj2][1]);
            pa[kj2][1] = pack2(sfr[2 * kj2][2],     sfr[2 * kj2][3]);
            pa[kj2][2] = pack2(sfr[2 * kj2 + 1][0], sfr[2 * kj2 + 1][1]);
            pa[kj2][3] = pack2(sfr[2 * kj2 + 1][2], sfr[2 * kj2 + 1][3]);
        }

        // O += P @ V
        #pragma unroll
        for (int kj2 = 0; kj2 < 4; kj2++) {
            #pragma unroll
            for (int db = 0; db < 4; db++) {
                unsigned u0, u1, u2, u3;
                ldsm4t(u0, u1, u2, u3, sa(&Vb[(16 * kj2 + trR) * ALD + 16 * db + trC]));
                unsigned bf0[2] = { u0, u1 }, bf1[2] = { u2, u3 };
                mma16(ofr[2 * db],     pa[kj2], bf0, ofr[2 * db]);
                mma16(ofr[2 * db + 1], pa[kj2], bf1, ofr[2 * db + 1]);
            }
        }
    }

    const int g = lane >> 2, q = lane & 3;
    float inv0 = 1.0f / l0, inv1 = 1.0f / l1;
    #pragma unroll
    for (int ni = 0; ni < 8; ni++) {
        int col = 8 * ni + 2 * q;
        *(__half2*)((__half*)Og + base + (size_t)(qt + wm + g) * C_ + col) =
            __floats2half2_rn(ofr[ni][0] * inv0, ofr[ni][1] * inv0);
        *(__half2*)((__half*)Og + base + (size_t)(qt + wm + g + 8) * C_ + col) =
            __floats2half2_rn(ofr[ni][2] * inv1, ofr[ni][3] * inv1);
    }
}

// ---------------------------------------------------------------------------
extern "C" void kernel_launch(void* const* d_in, const int* in_sizes, int n_in,
                              void* d_out, int out_size)
{
    const float* x  = (const float*)d_in[0];
    const float* Wq = (const float*)d_in[1];
    const float* bq = (const float*)d_in[2];
    const float* Wk = (const float*)d_in[3];
    const float* bk = (const float*)d_in[4];
    const float* Wv = (const float*)d_in[5];
    const float* bv = (const float*)d_in[6];
    const float* Wp = (const float*)d_in[7];
    float* out = (float*)d_out;

    __half *xh, *wq, *wk, *wv, *wp, *qh, *kh, *vh, *ah;
    cudaGetSymbolAddress((void**)&xh, g_xh);
    cudaGetSymbolAddress((void**)&wq, g_wq);
    cudaGetSymbolAddress((void**)&wk, g_wk);
    cudaGetSymbolAddress((void**)&wv, g_wv);
    cudaGetSymbolAddress((void**)&wp, g_wp);
    cudaGetSymbolAddress((void**)&qh, g_qh);
    cudaGetSymbolAddress((void**)&kh, g_kh);
    cudaGetSymbolAddress((void**)&vh, g_vh);
    cudaGetSymbolAddress((void**)&ah, g_ah);

    {
        int tot4 = X4 + 4 * W4;
        f2h_all<<<(tot4 + 255) / 256, 256>>>(x, Wq, Wk, Wv, Wp,
                                             xh, wq, wk, wv, wp);
    }

    const int qkv_smem = (256 + 384) * GLD * (int)sizeof(__half);   // 92160
    cudaFuncSetAttribute(gemm_qkv,
                         cudaFuncAttributeMaxDynamicSharedMemorySize, qkv_smem);
    gemm_qkv<<<dim3(C_ / 64, M_TOT / 128), 256, qkv_smem>>>(
        xh, wq, wk, wv, bq, bk, bv, qh, kh, vh);

    const int attn_smem = (128 + 6 * 64) * ALD * (int)sizeof(__half); // 73728
    cudaFuncSetAttribute(attn_h,
                         cudaFuncAttributeMaxDynamicSharedMemorySize, attn_smem);
    attn_h<<<dim3(T_ / 128, H_, B_), 256, attn_smem>>>(qh, kh, vh, ah);

    const int proj_smem = (256 + 256) * GLD * (int)sizeof(__half);  // 73728
    cudaFuncSetAttribute(gemm_proj,
                         cudaFuncAttributeMaxDynamicSharedMemorySize, proj_smem);
    gemm_proj<<<dim3(C_ / 128, M_TOT / 128), 256, proj_smem>>>(ah, wp, out);
}